// round 1
// baseline (speedup 1.0000x reference)
#include <cuda_runtime.h>
#include <math.h>
#include <stdint.h>

// Problem constants
#define B_  2
#define H_  16
#define L_  2048
#define S_  2048
#define D_  64
#define E_  1024
#define BH_ (B_*H_)

// ---------------- scratch (single __device__ array, offsets in floats) -----
// E matrix: 32*2048*2048           = 134217728
// aq/av/bq/bv/actx/bctx: 6x 32*2048*64 = 6*4194304
// rs/cs: 2x 65536
static const size_t OFF_E    = 0;
static const size_t OFF_AQ   = 134217728;
static const size_t OFF_AV   = OFF_AQ  + 4194304;
static const size_t OFF_BQ   = OFF_AV  + 4194304;
static const size_t OFF_BV   = OFF_BQ  + 4194304;
static const size_t OFF_ACTX = OFF_BV  + 4194304;
static const size_t OFF_BCTX = OFF_ACTX+ 4194304;
static const size_t OFF_RS   = OFF_BCTX+ 4194304;
static const size_t OFF_CS   = OFF_RS  + 65536;
static const size_t SCRATCH_ELEMS = OFF_CS + 65536;   // ~638 MB

__device__ float g_scratch[SCRATCH_ELEMS];

// ---------------- fast exp on FMA pipe (avoids MUFU throughput wall) -------
__device__ __forceinline__ float fexp(float x) {
    const float L2E = 1.4426950408889634f;
    const float LN2 = 0.6931471805599453f;
    float t = x * L2E;
    float r = rintf(t);
    float y = fmaf(-r, LN2, x);               // |y| <= 0.3466
    float p = 8.3333333e-3f;                  // 1/120
    p = fmaf(p, y, 4.1666667e-2f);            // 1/24
    p = fmaf(p, y, 1.6666667e-1f);            // 1/6
    p = fmaf(p, y, 0.5f);
    p = fmaf(p, y, 1.0f);
    p = fmaf(p, y, 1.0f);
    int e = (((int)r) + 127) << 23;
    return p * __int_as_float(e);
}

// ---------------- projection GEMM: Y = X@W + bias -> head layout -----------
// X: [B*2048, E] row-major. Out: [B,H,2048,D] contiguous.
// 128x128 tile, BK=8, 256 threads, 8x8 per thread.
__global__ __launch_bounds__(256) void proj_kernel(
    const float* __restrict__ X, const float* __restrict__ W,
    const float* __restrict__ bias, float* __restrict__ out)
{
    __shared__ float As[8][128];
    __shared__ float Bs[8][128];
    const int tid  = threadIdx.x;
    const int row0 = blockIdx.y * 128;
    const int col0 = blockIdx.x * 128;
    const int aRow = tid >> 1;
    const int aCol = (tid & 1) * 4;
    const int bRow = tid >> 5;
    const int bCol = (tid & 31) * 4;
    const int tr = (tid >> 4) * 8;
    const int tc = (tid & 15) * 8;
    float acc[8][8] = {};
    for (int k0 = 0; k0 < E_; k0 += 8) {
        float4 a4 = *reinterpret_cast<const float4*>(X + (size_t)(row0 + aRow) * E_ + k0 + aCol);
        As[aCol + 0][aRow] = a4.x; As[aCol + 1][aRow] = a4.y;
        As[aCol + 2][aRow] = a4.z; As[aCol + 3][aRow] = a4.w;
        *reinterpret_cast<float4*>(&Bs[bRow][bCol]) =
            *reinterpret_cast<const float4*>(W + (size_t)(k0 + bRow) * E_ + col0 + bCol);
        __syncthreads();
        #pragma unroll
        for (int k = 0; k < 8; k++) {
            float ar[8], br[8];
            *reinterpret_cast<float4*>(ar)     = *reinterpret_cast<const float4*>(&As[k][tr]);
            *reinterpret_cast<float4*>(ar + 4) = *reinterpret_cast<const float4*>(&As[k][tr + 4]);
            *reinterpret_cast<float4*>(br)     = *reinterpret_cast<const float4*>(&Bs[k][tc]);
            *reinterpret_cast<float4*>(br + 4) = *reinterpret_cast<const float4*>(&Bs[k][tc + 4]);
            #pragma unroll
            for (int i = 0; i < 8; i++)
                #pragma unroll
                for (int j = 0; j < 8; j++)
                    acc[i][j] = fmaf(ar[i], br[j], acc[i][j]);
        }
        __syncthreads();
    }
    #pragma unroll
    for (int i = 0; i < 8; i++) {
        int m  = row0 + tr + i;
        int b  = m >> 11;          // / 2048
        int ii = m & 2047;
        #pragma unroll
        for (int j = 0; j < 8; j++) {
            int c = col0 + tc + j;
            int h = c >> 6;
            int d = c & 63;
            out[(((size_t)b * H_ + h) * 2048 + ii) * D_ + d] = acc[i][j] + bias[c];
        }
    }
}

// ---------------- scores + fused exp: E = exp(scale * aq @ bq^T) -----------
// per (b,h): M=L, N=S, K=64. 128x128 tile, BK=16.
__global__ __launch_bounds__(256) void scores_exp_kernel(
    const float* __restrict__ aq, const float* __restrict__ bq, float* __restrict__ Eo)
{
    const int bh = blockIdx.z;
    const float* A  = aq + (size_t)bh * L_ * D_;
    const float* Bq = bq + (size_t)bh * S_ * D_;
    float* O = Eo + (size_t)bh * L_ * S_;
    __shared__ float As[16][128];
    __shared__ float Bs[16][128];
    const int tid  = threadIdx.x;
    const int row0 = blockIdx.y * 128;   // l
    const int col0 = blockIdx.x * 128;   // s
    const int lr = tid >> 2;             // 0..63
    const int lc = (tid & 3) * 4;        // 0,4,8,12
    const int tr = (tid >> 4) * 8;
    const int tc = (tid & 15) * 8;
    float acc[8][8] = {};
    #pragma unroll
    for (int k0 = 0; k0 < D_; k0 += 16) {
        #pragma unroll
        for (int r = 0; r < 2; r++) {
            float4 a4 = *reinterpret_cast<const float4*>(A  + (size_t)(row0 + lr + r * 64) * D_ + k0 + lc);
            As[lc + 0][lr + r * 64] = a4.x; As[lc + 1][lr + r * 64] = a4.y;
            As[lc + 2][lr + r * 64] = a4.z; As[lc + 3][lr + r * 64] = a4.w;
            float4 b4 = *reinterpret_cast<const float4*>(Bq + (size_t)(col0 + lr + r * 64) * D_ + k0 + lc);
            Bs[lc + 0][lr + r * 64] = b4.x; Bs[lc + 1][lr + r * 64] = b4.y;
            Bs[lc + 2][lr + r * 64] = b4.z; Bs[lc + 3][lr + r * 64] = b4.w;
        }
        __syncthreads();
        #pragma unroll
        for (int k = 0; k < 16; k++) {
            float ar[8], br[8];
            *reinterpret_cast<float4*>(ar)     = *reinterpret_cast<const float4*>(&As[k][tr]);
            *reinterpret_cast<float4*>(ar + 4) = *reinterpret_cast<const float4*>(&As[k][tr + 4]);
            *reinterpret_cast<float4*>(br)     = *reinterpret_cast<const float4*>(&Bs[k][tc]);
            *reinterpret_cast<float4*>(br + 4) = *reinterpret_cast<const float4*>(&Bs[k][tc + 4]);
            #pragma unroll
            for (int i = 0; i < 8; i++)
                #pragma unroll
                for (int j = 0; j < 8; j++)
                    acc[i][j] = fmaf(ar[i], br[j], acc[i][j]);
        }
        __syncthreads();
    }
    const float sc = 0.125f;   // 1/sqrt(64)
    #pragma unroll
    for (int i = 0; i < 8; i++) {
        size_t base = (size_t)(row0 + tr + i) * S_ + col0 + tc;
        float4 v0, v1;
        v0.x = fexp(acc[i][0] * sc); v0.y = fexp(acc[i][1] * sc);
        v0.z = fexp(acc[i][2] * sc); v0.w = fexp(acc[i][3] * sc);
        v1.x = fexp(acc[i][4] * sc); v1.y = fexp(acc[i][5] * sc);
        v1.z = fexp(acc[i][6] * sc); v1.w = fexp(acc[i][7] * sc);
        *reinterpret_cast<float4*>(O + base)     = v0;
        *reinterpret_cast<float4*>(O + base + 4) = v1;
    }
}

// ---------------- row sums (over s) ----------------------------------------
__global__ __launch_bounds__(256) void rowsum_kernel(
    const float* __restrict__ Eo, float* __restrict__ rs)
{
    const size_t row = blockIdx.x;
    const float* p = Eo + row * S_;
    float s = 0.0f;
    #pragma unroll
    for (int i = 0; i < 8; i++) s += p[threadIdx.x + i * 256];
    __shared__ float red[256];
    red[threadIdx.x] = s; __syncthreads();
    for (int st = 128; st > 0; st >>= 1) {
        if (threadIdx.x < st) red[threadIdx.x] += red[threadIdx.x + st];
        __syncthreads();
    }
    if (threadIdx.x == 0) rs[row] = red[0];
}

// ---------------- col sums (over l) ----------------------------------------
__global__ __launch_bounds__(256) void colsum_kernel(
    const float* __restrict__ Eo, float* __restrict__ cs)
{
    const int bh = blockIdx.y;
    const int s  = blockIdx.x * 256 + threadIdx.x;
    const float* p = Eo + (size_t)bh * L_ * S_ + s;
    float a0 = 0, a1 = 0, a2 = 0, a3 = 0;
    for (int l = 0; l < L_; l += 4) {
        a0 += p[(size_t)(l + 0) * S_];
        a1 += p[(size_t)(l + 1) * S_];
        a2 += p[(size_t)(l + 2) * S_];
        a3 += p[(size_t)(l + 3) * S_];
    }
    cs[bh * S_ + s] = (a0 + a1) + (a2 + a3);
}

// ---------------- context A: a_ctx[l,d] = (E[l,:] @ bv[:,d]) / rs[l] --------
// per (b,h): M=L, N=D=64, K=S. 64x64 tile, BK=16, 4x4/thread.
__global__ __launch_bounds__(256) void ctxA_kernel(
    const float* __restrict__ Eo, const float* __restrict__ V,
    const float* __restrict__ rs, float* __restrict__ out)
{
    const int bh = blockIdx.y;
    const float* Eb = Eo + (size_t)bh * L_ * S_;
    const float* Vb = V  + (size_t)bh * S_ * D_;
    float* O = out + (size_t)bh * L_ * D_;
    const float* R = rs + bh * L_;
    __shared__ float As[16][64];
    __shared__ float Bs[16][64];
    const int tid  = threadIdx.x;
    const int row0 = blockIdx.x * 64;
    const int tr = (tid >> 4) * 4, tc = (tid & 15) * 4;
    float acc[4][4] = {};
    for (int k0 = 0; k0 < S_; k0 += 16) {
        {
            int r = tid >> 2, c4 = (tid & 3) * 4;
            float4 a4 = *reinterpret_cast<const float4*>(Eb + (size_t)(row0 + r) * S_ + k0 + c4);
            As[c4 + 0][r] = a4.x; As[c4 + 1][r] = a4.y; As[c4 + 2][r] = a4.z; As[c4 + 3][r] = a4.w;
        }
        {
            int r = tid >> 4, c4 = (tid & 15) * 4;
            *reinterpret_cast<float4*>(&Bs[r][c4]) =
                *reinterpret_cast<const float4*>(Vb + (size_t)(k0 + r) * D_ + c4);
        }
        __syncthreads();
        #pragma unroll
        for (int k = 0; k < 16; k++) {
            float ar[4], br[4];
            *reinterpret_cast<float4*>(ar) = *reinterpret_cast<const float4*>(&As[k][tr]);
            *reinterpret_cast<float4*>(br) = *reinterpret_cast<const float4*>(&Bs[k][tc]);
            #pragma unroll
            for (int i = 0; i < 4; i++)
                #pragma unroll
                for (int j = 0; j < 4; j++)
                    acc[i][j] = fmaf(ar[i], br[j], acc[i][j]);
        }
        __syncthreads();
    }
    #pragma unroll
    for (int i = 0; i < 4; i++) {
        float inv = 1.0f / R[row0 + tr + i];
        float4 o;
        o.x = acc[i][0] * inv; o.y = acc[i][1] * inv;
        o.z = acc[i][2] * inv; o.w = acc[i][3] * inv;
        *reinterpret_cast<float4*>(O + (size_t)(row0 + tr + i) * D_ + tc) = o;
    }
}

// ---------------- context B: b_ctx[s,d] = (E[:,s] . av[:,d]) / cs[s] --------
// A accessed transposed (k = l). M=S, N=D, K=L.
__global__ __launch_bounds__(256) void ctxB_kernel(
    const float* __restrict__ Eo, const float* __restrict__ V,
    const float* __restrict__ cs, float* __restrict__ out)
{
    const int bh = blockIdx.y;
    const float* Eb = Eo + (size_t)bh * L_ * S_;
    const float* Vb = V  + (size_t)bh * L_ * D_;
    float* O = out + (size_t)bh * S_ * D_;
    const float* C = cs + bh * S_;
    __shared__ float As[16][64];
    __shared__ float Bs[16][64];
    const int tid  = threadIdx.x;
    const int row0 = blockIdx.x * 64;   // s block
    const int tr = (tid >> 4) * 4, tc = (tid & 15) * 4;
    float acc[4][4] = {};
    for (int k0 = 0; k0 < L_; k0 += 16) {
        {
            int r = tid >> 4, c4 = (tid & 15) * 4;
            *reinterpret_cast<float4*>(&As[r][c4]) =
                *reinterpret_cast<const float4*>(Eb + (size_t)(k0 + r) * S_ + row0 + c4);
        }
        {
            int r = tid >> 4, c4 = (tid & 15) * 4;
            *reinterpret_cast<float4*>(&Bs[r][c4]) =
                *reinterpret_cast<const float4*>(Vb + (size_t)(k0 + r) * D_ + c4);
        }
        __syncthreads();
        #pragma unroll
        for (int k = 0; k < 16; k++) {
            float ar[4], br[4];
            *reinterpret_cast<float4*>(ar) = *reinterpret_cast<const float4*>(&As[k][tr]);
            *reinterpret_cast<float4*>(br) = *reinterpret_cast<const float4*>(&Bs[k][tc]);
            #pragma unroll
            for (int i = 0; i < 4; i++)
                #pragma unroll
                for (int j = 0; j < 4; j++)
                    acc[i][j] = fmaf(ar[i], br[j], acc[i][j]);
        }
        __syncthreads();
    }
    #pragma unroll
    for (int i = 0; i < 4; i++) {
        float inv = 1.0f / C[row0 + tr + i];
        float4 o;
        o.x = acc[i][0] * inv; o.y = acc[i][1] * inv;
        o.z = acc[i][2] * inv; o.w = acc[i][3] * inv;
        *reinterpret_cast<float4*>(O + (size_t)(row0 + tr + i) * D_ + tc) = o;
    }
}

// ---------------- output projection: out = gather(ctx) @ W + bias ----------
// ctx in head layout [B,H,2048,D]; A[m,k] gathered; out row-major [B*2048, E].
__global__ __launch_bounds__(256) void outproj_kernel(
    const float* __restrict__ ctx, const float* __restrict__ W,
    const float* __restrict__ bias, float* __restrict__ out)
{
    __shared__ float As[8][128];
    __shared__ float Bs[8][128];
    const int tid  = threadIdx.x;
    const int row0 = blockIdx.y * 128;
    const int col0 = blockIdx.x * 128;
    const int aRow = tid >> 1;
    const int aCol = (tid & 1) * 4;
    const int bRow = tid >> 5;
    const int bCol = (tid & 31) * 4;
    const int tr = (tid >> 4) * 8;
    const int tc = (tid & 15) * 8;
    float acc[8][8] = {};
    const int m  = row0 + aRow;
    const int bb = m >> 11;
    const int ii = m & 2047;
    for (int k0 = 0; k0 < E_; k0 += 8) {
        int k = k0 + aCol;
        int h = k >> 6;
        int d = k & 63;
        float4 a4 = *reinterpret_cast<const float4*>(
            ctx + (((size_t)bb * H_ + h) * 2048 + ii) * D_ + d);
        As[aCol + 0][aRow] = a4.x; As[aCol + 1][aRow] = a4.y;
        As[aCol + 2][aRow] = a4.z; As[aCol + 3][aRow] = a4.w;
        *reinterpret_cast<float4*>(&Bs[bRow][bCol]) =
            *reinterpret_cast<const float4*>(W + (size_t)(k0 + bRow) * E_ + col0 + bCol);
        __syncthreads();
        #pragma unroll
        for (int kk = 0; kk < 8; kk++) {
            float ar[8], br[8];
            *reinterpret_cast<float4*>(ar)     = *reinterpret_cast<const float4*>(&As[kk][tr]);
            *reinterpret_cast<float4*>(ar + 4) = *reinterpret_cast<const float4*>(&As[kk][tr + 4]);
            *reinterpret_cast<float4*>(br)     = *reinterpret_cast<const float4*>(&Bs[kk][tc]);
            *reinterpret_cast<float4*>(br + 4) = *reinterpret_cast<const float4*>(&Bs[kk][tc + 4]);
            #pragma unroll
            for (int i = 0; i < 8; i++)
                #pragma unroll
                for (int j = 0; j < 8; j++)
                    acc[i][j] = fmaf(ar[i], br[j], acc[i][j]);
        }
        __syncthreads();
    }
    #pragma unroll
    for (int i = 0; i < 8; i++) {
        size_t om = (size_t)(row0 + tr + i) * E_;
        #pragma unroll
        for (int j = 0; j < 8; j++) {
            int c = col0 + tc + j;
            out[om + c] = acc[i][j] + bias[c];
        }
    }
}

// ---------------------------------------------------------------------------
extern "C" void kernel_launch(void* const* d_in, const int* in_sizes, int n_in,
                              void* d_out, int out_size)
{
    (void)in_sizes; (void)n_in; (void)out_size;
    const float* a     = (const float*)d_in[0];
    const float* b     = (const float*)d_in[1];
    const float* Wa_qk = (const float*)d_in[2];
    const float* ba_qk = (const float*)d_in[3];
    const float* Wa_v  = (const float*)d_in[4];
    const float* ba_v  = (const float*)d_in[5];
    const float* Wb_qk = (const float*)d_in[6];
    const float* bb_qk = (const float*)d_in[7];
    const float* Wb_v  = (const float*)d_in[8];
    const float* bb_v  = (const float*)d_in[9];
    const float* Wa_o  = (const float*)d_in[10];
    const float* ba_o  = (const float*)d_in[11];
    const float* Wb_o  = (const float*)d_in[12];
    const float* bb_o  = (const float*)d_in[13];
    float* out = (float*)d_out;

    float* scratch = nullptr;
    cudaGetSymbolAddress((void**)&scratch, g_scratch);
    float* Ebuf = scratch + OFF_E;
    float* aq   = scratch + OFF_AQ;
    float* av   = scratch + OFF_AV;
    float* bq   = scratch + OFF_BQ;
    float* bv   = scratch + OFF_BV;
    float* actx = scratch + OFF_ACTX;
    float* bctx = scratch + OFF_BCTX;
    float* rs   = scratch + OFF_RS;
    float* cs   = scratch + OFF_CS;

    dim3 pg(E_ / 128, (B_ * 2048) / 128);        // (8, 32)
    proj_kernel<<<pg, 256>>>(a, Wa_qk, ba_qk, aq);
    proj_kernel<<<pg, 256>>>(a, Wa_v,  ba_v,  av);
    proj_kernel<<<pg, 256>>>(b, Wb_qk, bb_qk, bq);
    proj_kernel<<<pg, 256>>>(b, Wb_v,  bb_v,  bv);

    dim3 sg(S_ / 128, L_ / 128, BH_);            // (16, 16, 32)
    scores_exp_kernel<<<sg, 256>>>(aq, bq, Ebuf);

    rowsum_kernel<<<BH_ * L_, 256>>>(Ebuf, rs);
    colsum_kernel<<<dim3(S_ / 256, BH_), 256>>>(Ebuf, cs);

    ctxA_kernel<<<dim3(L_ / 64, BH_), 256>>>(Ebuf, bv, rs, actx);
    ctxB_kernel<<<dim3(S_ / 64, BH_), 256>>>(Ebuf, av, cs, bctx);

    outproj_kernel<<<pg, 256>>>(actx, Wa_o, ba_o, out);
    outproj_kernel<<<pg, 256>>>(bctx, Wb_o, bb_o, out + (size_t)B_ * L_ * E_);
}

// round 2
// speedup vs baseline: 1.3468x; 1.3468x over previous
#include <cuda_runtime.h>
#include <math.h>
#include <stdint.h>

#define B_  2
#define H_  16
#define L_  2048
#define S_  2048
#define D_  64
#define E_  1024
#define BH_ (B_*H_)

// ---------------- scratch ---------------------------------------------------
static const size_t OFF_E    = 0;
static const size_t OFF_AQ   = 134217728;
static const size_t OFF_AV   = OFF_AQ  + 4194304;
static const size_t OFF_BQ   = OFF_AV  + 4194304;
static const size_t OFF_BV   = OFF_BQ  + 4194304;
static const size_t OFF_ACTX = OFF_BV  + 4194304;
static const size_t OFF_BCTX = OFF_ACTX+ 4194304;
static const size_t OFF_RS   = OFF_BCTX+ 4194304;
static const size_t OFF_CS   = OFF_RS  + 65536;
static const size_t SCRATCH_ELEMS = OFF_CS + 65536;

__device__ float g_scratch[SCRATCH_ELEMS];

// ---------------- fast exp on FMA pipe -------------------------------------
__device__ __forceinline__ float fexp(float x) {
    const float L2E = 1.4426950408889634f;
    const float LN2 = 0.6931471805599453f;
    float t = x * L2E;
    float r = rintf(t);
    float y = fmaf(-r, LN2, x);
    float p = 8.3333333e-3f;
    p = fmaf(p, y, 4.1666667e-2f);
    p = fmaf(p, y, 1.6666667e-1f);
    p = fmaf(p, y, 0.5f);
    p = fmaf(p, y, 1.0f);
    p = fmaf(p, y, 1.0f);
    int e = (((int)r) + 127) << 23;
    return p * __int_as_float(e);
}

// ---------------- zero init for rs/cs ---------------------------------------
__global__ void zero_kernel(float* p, int n) {
    int i = blockIdx.x * blockDim.x + threadIdx.x;
    if (i < n) p[i] = 0.0f;
}

// ---------------- 4-way projection GEMM (double-buffered) -------------------
struct ProjArgs { const float* X; const float* W; const float* bias; float* out; };
struct ProjArgs4 { ProjArgs p[4]; };

__global__ __launch_bounds__(256) void proj_kernel(ProjArgs4 args)
{
    const ProjArgs pa = args.p[blockIdx.z];
    const float* __restrict__ X = pa.X;
    const float* __restrict__ W = pa.W;
    const float* __restrict__ bias = pa.bias;
    float* __restrict__ out = pa.out;

    __shared__ float As[2][8][128];
    __shared__ float Bs[2][8][128];
    const int tid  = threadIdx.x;
    const int row0 = blockIdx.y * 128;
    const int col0 = blockIdx.x * 128;
    const int aRow = tid >> 1;
    const int aCol = (tid & 1) * 4;
    const int bRow = tid >> 5;
    const int bCol = (tid & 31) * 4;
    const int tr = (tid >> 4) * 8;
    const int tc = (tid & 15) * 8;
    float acc[8][8] = {};

    const float* Aptr = X + (size_t)(row0 + aRow) * E_ + aCol;
    const float* Bptr = W + (size_t)bRow * E_ + col0 + bCol;

    // preload tile 0
    {
        float4 a4 = *reinterpret_cast<const float4*>(Aptr);
        float4 b4 = *reinterpret_cast<const float4*>(Bptr);
        As[0][aCol + 0][aRow] = a4.x; As[0][aCol + 1][aRow] = a4.y;
        As[0][aCol + 2][aRow] = a4.z; As[0][aCol + 3][aRow] = a4.w;
        *reinterpret_cast<float4*>(&Bs[0][bRow][bCol]) = b4;
    }
    __syncthreads();

    int buf = 0;
    for (int k0 = 8; k0 <= E_; k0 += 8) {
        float4 na, nb;
        bool more = (k0 < E_);
        if (more) {
            na = *reinterpret_cast<const float4*>(Aptr + k0);
            nb = *reinterpret_cast<const float4*>(Bptr + (size_t)k0 * E_);
        }
        #pragma unroll
        for (int k = 0; k < 8; k++) {
            float ar[8], br[8];
            *reinterpret_cast<float4*>(ar)     = *reinterpret_cast<const float4*>(&As[buf][k][tr]);
            *reinterpret_cast<float4*>(ar + 4) = *reinterpret_cast<const float4*>(&As[buf][k][tr + 4]);
            *reinterpret_cast<float4*>(br)     = *reinterpret_cast<const float4*>(&Bs[buf][k][tc]);
            *reinterpret_cast<float4*>(br + 4) = *reinterpret_cast<const float4*>(&Bs[buf][k][tc + 4]);
            #pragma unroll
            for (int i = 0; i < 8; i++)
                #pragma unroll
                for (int j = 0; j < 8; j++)
                    acc[i][j] = fmaf(ar[i], br[j], acc[i][j]);
        }
        if (more) {
            int nb_ = buf ^ 1;
            As[nb_][aCol + 0][aRow] = na.x; As[nb_][aCol + 1][aRow] = na.y;
            As[nb_][aCol + 2][aRow] = na.z; As[nb_][aCol + 3][aRow] = na.w;
            *reinterpret_cast<float4*>(&Bs[nb_][bRow][bCol]) = nb;
        }
        __syncthreads();
        buf ^= 1;
    }

    #pragma unroll
    for (int i = 0; i < 8; i++) {
        int m  = row0 + tr + i;
        int b  = m >> 11;
        int ii = m & 2047;
        #pragma unroll
        for (int j = 0; j < 8; j++) {
            int c = col0 + tc + j;
            int h = c >> 6;
            int d = c & 63;
            out[(((size_t)b * H_ + h) * 2048 + ii) * D_ + d] = acc[i][j] + bias[c];
        }
    }
}

// ---------------- scores + exp + fused row/col sums -------------------------
__global__ __launch_bounds__(256) void scores_exp_kernel(
    const float* __restrict__ aq, const float* __restrict__ bq,
    float* __restrict__ Eo, float* __restrict__ rs, float* __restrict__ cs)
{
    const int bh = blockIdx.z;
    const float* A  = aq + (size_t)bh * L_ * D_;
    const float* Bq = bq + (size_t)bh * S_ * D_;
    float* O = Eo + (size_t)bh * L_ * S_;
    __shared__ float As[16][128];
    __shared__ float Bs[16][128];
    __shared__ float colred[16][128];
    const int tid  = threadIdx.x;
    const int row0 = blockIdx.y * 128;
    const int col0 = blockIdx.x * 128;
    const int lr = tid >> 2;
    const int lc = (tid & 3) * 4;
    const int tr = (tid >> 4) * 8;
    const int tc = (tid & 15) * 8;
    float acc[8][8] = {};
    #pragma unroll
    for (int k0 = 0; k0 < D_; k0 += 16) {
        #pragma unroll
        for (int r = 0; r < 2; r++) {
            float4 a4 = *reinterpret_cast<const float4*>(A  + (size_t)(row0 + lr + r * 64) * D_ + k0 + lc);
            As[lc + 0][lr + r * 64] = a4.x; As[lc + 1][lr + r * 64] = a4.y;
            As[lc + 2][lr + r * 64] = a4.z; As[lc + 3][lr + r * 64] = a4.w;
            float4 b4 = *reinterpret_cast<const float4*>(Bq + (size_t)(col0 + lr + r * 64) * D_ + k0 + lc);
            Bs[lc + 0][lr + r * 64] = b4.x; Bs[lc + 1][lr + r * 64] = b4.y;
            Bs[lc + 2][lr + r * 64] = b4.z; Bs[lc + 3][lr + r * 64] = b4.w;
        }
        __syncthreads();
        #pragma unroll
        for (int k = 0; k < 16; k++) {
            float ar[8], br[8];
            *reinterpret_cast<float4*>(ar)     = *reinterpret_cast<const float4*>(&As[k][tr]);
            *reinterpret_cast<float4*>(ar + 4) = *reinterpret_cast<const float4*>(&As[k][tr + 4]);
            *reinterpret_cast<float4*>(br)     = *reinterpret_cast<const float4*>(&Bs[k][tc]);
            *reinterpret_cast<float4*>(br + 4) = *reinterpret_cast<const float4*>(&Bs[k][tc + 4]);
            #pragma unroll
            for (int i = 0; i < 8; i++)
                #pragma unroll
                for (int j = 0; j < 8; j++)
                    acc[i][j] = fmaf(ar[i], br[j], acc[i][j]);
        }
        __syncthreads();
    }
    const float sc = 0.125f;
    float cj[8] = {};
    #pragma unroll
    for (int i = 0; i < 8; i++) {
        float e[8];
        #pragma unroll
        for (int j = 0; j < 8; j++) e[j] = fexp(acc[i][j] * sc);
        size_t base = (size_t)(row0 + tr + i) * S_ + col0 + tc;
        float4 v0, v1;
        v0.x = e[0]; v0.y = e[1]; v0.z = e[2]; v0.w = e[3];
        v1.x = e[4]; v1.y = e[5]; v1.z = e[6]; v1.w = e[7];
        *reinterpret_cast<float4*>(O + base)     = v0;
        *reinterpret_cast<float4*>(O + base + 4) = v1;
        float rsum = ((e[0] + e[1]) + (e[2] + e[3])) + ((e[4] + e[5]) + (e[6] + e[7]));
        #pragma unroll
        for (int off = 8; off; off >>= 1)
            rsum += __shfl_down_sync(0xffffffffu, rsum, off, 16);
        if ((tid & 15) == 0)
            atomicAdd(&rs[bh * L_ + row0 + tr + i], rsum);
        #pragma unroll
        for (int j = 0; j < 8; j++) cj[j] += e[j];
    }
    #pragma unroll
    for (int j = 0; j < 8; j++) colred[tid >> 4][tc + j] = cj[j];
    __syncthreads();
    if (tid < 128) {
        float s = 0.0f;
        #pragma unroll
        for (int g = 0; g < 16; g++) s += colred[g][tid];
        atomicAdd(&cs[bh * S_ + col0 + tid], s);
    }
}

// ---------------- combined context GEMM (z=0: ctxA, z=1: ctxB) --------------
// ctxA: out[l,d] = sum_s E[l,s] * bv[s,d] / rs[l]      (A row-major in k)
// ctxB: out[s,d] = sum_l E[l,s] * av[l,d] / cs[s]      (A transposed in k)
__global__ __launch_bounds__(256) void ctx_kernel(
    const float* __restrict__ Eo,
    const float* __restrict__ bv, const float* __restrict__ av,
    const float* __restrict__ rs, const float* __restrict__ cs,
    float* __restrict__ actx, float* __restrict__ bctx)
{
    const int bh = blockIdx.y;
    const int row0 = blockIdx.x * 128;
    const bool tb = (blockIdx.z != 0);
    const float* Eb  = Eo + (size_t)bh * L_ * S_;
    const float* Vb  = (tb ? av : bv) + (size_t)bh * 2048 * D_;
    const float* Nrm = (tb ? cs : rs) + bh * 2048;
    float* O = (tb ? bctx : actx) + (size_t)bh * 2048 * D_;

    __shared__ float As[2][16][128];
    __shared__ float Bs[2][16][64];
    const int tid = threadIdx.x;
    const int tr = (tid >> 4) * 8;
    const int tc = (tid & 15) * 4;
    float acc[8][4] = {};

    // A load indices
    const int ra0 = tid >> 2;            // ctxA: row (q adds 64)
    const int ca0 = (tid & 3) * 4;       // ctxA: k-offset
    const int kb0 = tid >> 5;            // ctxB: k row (q adds 8)
    const int cb0 = (tid & 31) * 4;      // ctxB: s-offset
    // B load indices
    const int rb = tid >> 4;
    const int cb = (tid & 15) * 4;

    // preload tile 0
    {
        if (!tb) {
            #pragma unroll
            for (int q = 0; q < 2; q++) {
                float4 a4 = *reinterpret_cast<const float4*>(Eb + (size_t)(row0 + ra0 + q * 64) * S_ + ca0);
                As[0][ca0 + 0][ra0 + q * 64] = a4.x; As[0][ca0 + 1][ra0 + q * 64] = a4.y;
                As[0][ca0 + 2][ra0 + q * 64] = a4.z; As[0][ca0 + 3][ra0 + q * 64] = a4.w;
            }
        } else {
            #pragma unroll
            for (int q = 0; q < 2; q++)
                *reinterpret_cast<float4*>(&As[0][kb0 + q * 8][cb0]) =
                    *reinterpret_cast<const float4*>(Eb + (size_t)(kb0 + q * 8) * S_ + row0 + cb0);
        }
        *reinterpret_cast<float4*>(&Bs[0][rb][cb]) =
            *reinterpret_cast<const float4*>(Vb + (size_t)rb * D_ + cb);
    }
    __syncthreads();

    int buf = 0;
    for (int k0 = 16; k0 <= 2048; k0 += 16) {
        float4 na0, na1, nb;
        bool more = (k0 < 2048);
        if (more) {
            if (!tb) {
                na0 = *reinterpret_cast<const float4*>(Eb + (size_t)(row0 + ra0)      * S_ + k0 + ca0);
                na1 = *reinterpret_cast<const float4*>(Eb + (size_t)(row0 + ra0 + 64) * S_ + k0 + ca0);
            } else {
                na0 = *reinterpret_cast<const float4*>(Eb + (size_t)(k0 + kb0)     * S_ + row0 + cb0);
                na1 = *reinterpret_cast<const float4*>(Eb + (size_t)(k0 + kb0 + 8) * S_ + row0 + cb0);
            }
            nb = *reinterpret_cast<const float4*>(Vb + (size_t)(k0 + rb) * D_ + cb);
        }
        #pragma unroll
        for (int k = 0; k < 16; k++) {
            float ar[8], br[4];
            *reinterpret_cast<float4*>(ar)     = *reinterpret_cast<const float4*>(&As[buf][k][tr]);
            *reinterpret_cast<float4*>(ar + 4) = *reinterpret_cast<const float4*>(&As[buf][k][tr + 4]);
            *reinterpret_cast<float4*>(br)     = *reinterpret_cast<const float4*>(&Bs[buf][k][tc]);
            #pragma unroll
            for (int i = 0; i < 8; i++)
                #pragma unroll
                for (int j = 0; j < 4; j++)
                    acc[i][j] = fmaf(ar[i], br[j], acc[i][j]);
        }
        if (more) {
            int nbuf = buf ^ 1;
            if (!tb) {
                As[nbuf][ca0 + 0][ra0] = na0.x; As[nbuf][ca0 + 1][ra0] = na0.y;
                As[nbuf][ca0 + 2][ra0] = na0.z; As[nbuf][ca0 + 3][ra0] = na0.w;
                As[nbuf][ca0 + 0][ra0 + 64] = na1.x; As[nbuf][ca0 + 1][ra0 + 64] = na1.y;
                As[nbuf][ca0 + 2][ra0 + 64] = na1.z; As[nbuf][ca0 + 3][ra0 + 64] = na1.w;
            } else {
                *reinterpret_cast<float4*>(&As[nbuf][kb0][cb0])     = na0;
                *reinterpret_cast<float4*>(&As[nbuf][kb0 + 8][cb0]) = na1;
            }
            *reinterpret_cast<float4*>(&Bs[nbuf][rb][cb]) = nb;
        }
        __syncthreads();
        buf ^= 1;
    }

    #pragma unroll
    for (int i = 0; i < 8; i++) {
        float inv = 1.0f / Nrm[row0 + tr + i];
        float4 o;
        o.x = acc[i][0] * inv; o.y = acc[i][1] * inv;
        o.z = acc[i][2] * inv; o.w = acc[i][3] * inv;
        *reinterpret_cast<float4*>(O + (size_t)(row0 + tr + i) * D_ + tc) = o;
    }
}

// ---------------- 2-way output projection (double-buffered) -----------------
struct OutArgs { const float* ctx; const float* W; const float* bias; float* out; };
struct OutArgs2 { OutArgs p[2]; };

__global__ __launch_bounds__(256) void outproj_kernel(OutArgs2 args)
{
    const OutArgs pa = args.p[blockIdx.z];
    const float* __restrict__ ctx  = pa.ctx;
    const float* __restrict__ W    = pa.W;
    const float* __restrict__ bias = pa.bias;
    float* __restrict__ out = pa.out;

    __shared__ float As[2][8][128];
    __shared__ float Bs[2][8][128];
    const int tid  = threadIdx.x;
    const int row0 = blockIdx.y * 128;
    const int col0 = blockIdx.x * 128;
    const int aRow = tid >> 1;
    const int aCol = (tid & 1) * 4;
    const int bRow = tid >> 5;
    const int bCol = (tid & 31) * 4;
    const int tr = (tid >> 4) * 8;
    const int tc = (tid & 15) * 8;
    float acc[8][8] = {};

    const int m  = row0 + aRow;
    const int bb = m >> 11;
    const int ii = m & 2047;
    const float* Abase = ctx + ((size_t)bb * H_ * 2048 + ii) * D_;
    const float* Bptr  = W + (size_t)bRow * E_ + col0 + bCol;

    // preload tile 0
    {
        int k = aCol;
        float4 a4 = *reinterpret_cast<const float4*>(Abase + (size_t)(k >> 6) * 2048 * D_ + (k & 63));
        float4 b4 = *reinterpret_cast<const float4*>(Bptr);
        As[0][aCol + 0][aRow] = a4.x; As[0][aCol + 1][aRow] = a4.y;
        As[0][aCol + 2][aRow] = a4.z; As[0][aCol + 3][aRow] = a4.w;
        *reinterpret_cast<float4*>(&Bs[0][bRow][bCol]) = b4;
    }
    __syncthreads();

    int buf = 0;
    for (int k0 = 8; k0 <= E_; k0 += 8) {
        float4 na, nb;
        bool more = (k0 < E_);
        if (more) {
            int k = k0 + aCol;
            na = *reinterpret_cast<const float4*>(Abase + (size_t)(k >> 6) * 2048 * D_ + (k & 63));
            nb = *reinterpret_cast<const float4*>(Bptr + (size_t)k0 * E_);
        }
        #pragma unroll
        for (int kk = 0; kk < 8; kk++) {
            float ar[8], br[8];
            *reinterpret_cast<float4*>(ar)     = *reinterpret_cast<const float4*>(&As[buf][kk][tr]);
            *reinterpret_cast<float4*>(ar + 4) = *reinterpret_cast<const float4*>(&As[buf][kk][tr + 4]);
            *reinterpret_cast<float4*>(br)     = *reinterpret_cast<const float4*>(&Bs[buf][kk][tc]);
            *reinterpret_cast<float4*>(br + 4) = *reinterpret_cast<const float4*>(&Bs[buf][kk][tc + 4]);
            #pragma unroll
            for (int i = 0; i < 8; i++)
                #pragma unroll
                for (int j = 0; j < 8; j++)
                    acc[i][j] = fmaf(ar[i], br[j], acc[i][j]);
        }
        if (more) {
            int nbuf = buf ^ 1;
            As[nbuf][aCol + 0][aRow] = na.x; As[nbuf][aCol + 1][aRow] = na.y;
            As[nbuf][aCol + 2][aRow] = na.z; As[nbuf][aCol + 3][aRow] = na.w;
            *reinterpret_cast<float4*>(&Bs[nbuf][bRow][bCol]) = nb;
        }
        __syncthreads();
        buf ^= 1;
    }

    #pragma unroll
    for (int i = 0; i < 8; i++) {
        size_t om = (size_t)(row0 + tr + i) * E_;
        #pragma unroll
        for (int j = 0; j < 8; j++) {
            int c = col0 + tc + j;
            out[om + c] = acc[i][j] + bias[c];
        }
    }
}

// ---------------------------------------------------------------------------
extern "C" void kernel_launch(void* const* d_in, const int* in_sizes, int n_in,
                              void* d_out, int out_size)
{
    (void)in_sizes; (void)n_in; (void)out_size;
    const float* a     = (const float*)d_in[0];
    const float* b     = (const float*)d_in[1];
    const float* Wa_qk = (const float*)d_in[2];
    const float* ba_qk = (const float*)d_in[3];
    const float* Wa_v  = (const float*)d_in[4];
    const float* ba_v  = (const float*)d_in[5];
    const float* Wb_qk = (const float*)d_in[6];
    const float* bb_qk = (const float*)d_in[7];
    const float* Wb_v  = (const float*)d_in[8];
    const float* bb_v  = (const float*)d_in[9];
    const float* Wa_o  = (const float*)d_in[10];
    const float* ba_o  = (const float*)d_in[11];
    const float* Wb_o  = (const float*)d_in[12];
    const float* bb_o  = (const float*)d_in[13];
    float* out = (float*)d_out;

    float* scratch = nullptr;
    cudaGetSymbolAddress((void**)&scratch, g_scratch);
    float* Ebuf = scratch + OFF_E;
    float* aq   = scratch + OFF_AQ;
    float* av   = scratch + OFF_AV;
    float* bq   = scratch + OFF_BQ;
    float* bv   = scratch + OFF_BV;
    float* actx = scratch + OFF_ACTX;
    float* bctx = scratch + OFF_BCTX;
    float* rs   = scratch + OFF_RS;
    float* cs   = scratch + OFF_CS;

    zero_kernel<<<512, 256>>>(rs, 131072);   // zeroes rs and cs (contiguous)

    ProjArgs4 pargs;
    pargs.p[0] = { a, Wa_qk, ba_qk, aq };
    pargs.p[1] = { a, Wa_v,  ba_v,  av };
    pargs.p[2] = { b, Wb_qk, bb_qk, bq };
    pargs.p[3] = { b, Wb_v,  bb_v,  bv };
    proj_kernel<<<dim3(E_ / 128, (B_ * 2048) / 128, 4), 256>>>(pargs);

    scores_exp_kernel<<<dim3(S_ / 128, L_ / 128, BH_), 256>>>(aq, bq, Ebuf, rs, cs);

    ctx_kernel<<<dim3(2048 / 128, BH_, 2), 256>>>(Ebuf, bv, av, rs, cs, actx, bctx);

    OutArgs2 oargs;
    oargs.p[0] = { actx, Wa_o, ba_o, out };
    oargs.p[1] = { bctx, Wb_o, bb_o, out + (size_t)B_ * L_ * E_ };
    outproj_kernel<<<dim3(E_ / 128, (B_ * 2048) / 128, 2), 256>>>(oargs);
}

// round 4
// speedup vs baseline: 1.5539x; 1.1538x over previous
#include <cuda_runtime.h>
#include <math.h>
#include <stdint.h>

#define B_    2
#define H_    16
#define E_    1024
#define D_    64
#define BH_   32
#define NSEQ  2048

// ---------------- scratch (floats) ------------------------------------------
static const size_t OFF_AQ   = 0;
static const size_t OFF_AV   = OFF_AQ  + 4194304;
static const size_t OFF_BQ   = OFF_AV  + 4194304;
static const size_t OFF_BV   = OFF_BQ  + 4194304;
static const size_t OFF_ACTX = OFF_BV  + 4194304;
static const size_t OFF_BCTX = OFF_ACTX+ 4194304;
static const size_t SCRATCH_ELEMS = OFF_BCTX + 4194304;

__device__ float g_scratch[SCRATCH_ELEMS];

// ---------------- fast exp on FMA pipe --------------------------------------
__device__ __forceinline__ float fexp(float x) {
    const float L2E = 1.4426950408889634f;
    const float LN2 = 0.6931471805599453f;
    float t = x * L2E;
    float r = rintf(t);
    float y = fmaf(-r, LN2, x);
    float p = 8.3333333e-3f;
    p = fmaf(p, y, 4.1666667e-2f);
    p = fmaf(p, y, 1.6666667e-1f);
    p = fmaf(p, y, 0.5f);
    p = fmaf(p, y, 1.0f);
    p = fmaf(p, y, 1.0f);
    int e = (((int)r) + 127) << 23;
    return p * __int_as_float(e);
}

__device__ __forceinline__ uint32_t to_tf32(float f) {
    uint32_t r;
    asm("cvt.rna.tf32.f32 %0, %1;" : "=r"(r) : "f"(f));
    return r;
}

// mma.sync m16n8k8 tf32 (portable PTX, works on non-'a' target)
__device__ __forceinline__ void mma_tf32(float c[4], const uint32_t a[4],
                                         uint32_t b0, uint32_t b1) {
    asm volatile(
        "mma.sync.aligned.m16n8k8.row.col.f32.tf32.tf32.f32 "
        "{%0,%1,%2,%3}, {%4,%5,%6,%7}, {%8,%9}, {%0,%1,%2,%3};"
        : "+f"(c[0]), "+f"(c[1]), "+f"(c[2]), "+f"(c[3])
        : "r"(a[0]), "r"(a[1]), "r"(a[2]), "r"(a[3]), "r"(b0), "r"(b1));
}

// smem float offsets / strides (pads chosen for conflict-free fragment LDS)
#define QSTR 68
#define KSTR 68
#define VSTR 72
#define PSTR 132
#define SQ_  0
#define SK_  (SQ_ + 128*QSTR)          // 8704
#define SV_  (SK_ + 128*KSTR)          // 17408
#define SP_  (SV_ + 128*VSTR)          // 26624
#define FLASH_FLOATS (SP_ + 128*PSTR)  // 43520 floats
#define FLASH_SMEM   (FLASH_FLOATS*4)  // 174080 bytes

// ---------------- fused flash kernel (scores->exp->ctx, both softmax sides) --
// Dual softmax has no max-subtraction and no rescaling: numerator and
// denominator are plain sums of exp, so per-row register sums suffice.
// Side 0: Q=aq,K=bq,V=bv -> actx (row softmax). Side 1: Q=bq,K=aq,V=av -> bctx.
__global__ __launch_bounds__(256) void flash_kernel(
    const float* __restrict__ aq, const float* __restrict__ bq,
    const float* __restrict__ av, const float* __restrict__ bv,
    float* __restrict__ actx, float* __restrict__ bctx)
{
    extern __shared__ float sm[];
    uint32_t* smu = reinterpret_cast<uint32_t*>(sm);

    const int tid  = threadIdx.x;
    const int lane = tid & 31;
    const int warp = tid >> 5;
    const int g = lane >> 2;      // groupID (0..7)
    const int t = lane & 3;       // threadID in group (0..3)
    const int m0 = warp * 16;     // query rows owned by this warp

    const int side = blockIdx.z;
    const int bh   = blockIdx.y;
    const int row0 = blockIdx.x * 128;

    const float* Qg = (side ? bq : aq) + (size_t)bh * NSEQ * D_;
    const float* Kg = (side ? aq : bq) + (size_t)bh * NSEQ * D_;
    const float* Vg = (side ? av : bv) + (size_t)bh * NSEQ * D_;
    float* Og = (side ? bctx : actx) + (size_t)bh * NSEQ * D_;

    // ---- load Q tile [128][64] as tf32, stride 68 ----
    {
        const float4* src = reinterpret_cast<const float4*>(Qg + (size_t)row0 * D_);
        #pragma unroll
        for (int i = 0; i < 8; i++) {
            int gi = i * 1024 + tid * 4;
            float4 v = src[gi >> 2];
            int r = gi >> 6, c = gi & 63;
            uint4 u = { to_tf32(v.x), to_tf32(v.y), to_tf32(v.z), to_tf32(v.w) };
            *reinterpret_cast<uint4*>(&smu[SQ_ + r * QSTR + c]) = u;
        }
    }
    __syncthreads();

    // ---- hoist Q fragments into registers (reused for all key tiles) ----
    uint32_t Qf[8][4];
    #pragma unroll
    for (int k = 0; k < 8; k++) {
        Qf[k][0] = smu[SQ_ + (m0 + g)     * QSTR + k * 8 + t];
        Qf[k][1] = smu[SQ_ + (m0 + g + 8) * QSTR + k * 8 + t];
        Qf[k][2] = smu[SQ_ + (m0 + g)     * QSTR + k * 8 + t + 4];
        Qf[k][3] = smu[SQ_ + (m0 + g + 8) * QSTR + k * 8 + t + 4];
    }

    float Oacc[8][4];
    #pragma unroll
    for (int n = 0; n < 8; n++)
        #pragma unroll
        for (int j = 0; j < 4; j++) Oacc[n][j] = 0.0f;
    float rsum0 = 0.0f, rsum1 = 0.0f;

    for (int kt = 0; kt < 16; kt++) {
        const int key0 = kt * 128;
        if (kt > 0) __syncthreads();   // all warps done reading K/V of prev tile

        // ---- load K [128][64] (stride 68) and V [128][64] (stride 72) ----
        {
            const float4* ks = reinterpret_cast<const float4*>(Kg + (size_t)key0 * D_);
            const float4* vs = reinterpret_cast<const float4*>(Vg + (size_t)key0 * D_);
            #pragma unroll
            for (int i = 0; i < 8; i++) {
                int gi = i * 1024 + tid * 4;
                int r = gi >> 6, c = gi & 63;
                float4 kv = ks[gi >> 2];
                uint4 ku = { to_tf32(kv.x), to_tf32(kv.y), to_tf32(kv.z), to_tf32(kv.w) };
                *reinterpret_cast<uint4*>(&smu[SK_ + r * KSTR + c]) = ku;
                float4 vv = vs[gi >> 2];
                uint4 vu = { to_tf32(vv.x), to_tf32(vv.y), to_tf32(vv.z), to_tf32(vv.w) };
                *reinterpret_cast<uint4*>(&smu[SV_ + r * VSTR + c]) = vu;
            }
        }
        __syncthreads();

        // ---- MMA1: S[16,128] = Q @ K^T, per n-tile; exp; P store; rowsum ----
        #pragma unroll
        for (int n = 0; n < 16; n++) {
            float c4[4] = {0.0f, 0.0f, 0.0f, 0.0f};
            #pragma unroll
            for (int k = 0; k < 8; k++) {
                uint32_t b0 = smu[SK_ + (n * 8 + g) * KSTR + k * 8 + t];
                uint32_t b1 = smu[SK_ + (n * 8 + g) * KSTR + k * 8 + t + 4];
                mma_tf32(c4, Qf[k], b0, b1);
            }
            float e0 = fexp(c4[0] * 0.125f);
            float e1 = fexp(c4[1] * 0.125f);
            float e2 = fexp(c4[2] * 0.125f);
            float e3 = fexp(c4[3] * 0.125f);
            rsum0 += e0 + e1;
            rsum1 += e2 + e3;
            uint2 lo = { to_tf32(e0), to_tf32(e1) };
            uint2 hi = { to_tf32(e2), to_tf32(e3) };
            *reinterpret_cast<uint2*>(&smu[SP_ + (m0 + g)     * PSTR + n * 8 + 2 * t]) = lo;
            *reinterpret_cast<uint2*>(&smu[SP_ + (m0 + g + 8) * PSTR + n * 8 + 2 * t]) = hi;
        }
        __syncwarp();   // P rows owned by this warp only

        // ---- MMA2: O[16,64] += P @ V ----
        #pragma unroll
        for (int k = 0; k < 16; k++) {
            uint32_t a[4];
            a[0] = smu[SP_ + (m0 + g)     * PSTR + k * 8 + t];
            a[1] = smu[SP_ + (m0 + g + 8) * PSTR + k * 8 + t];
            a[2] = smu[SP_ + (m0 + g)     * PSTR + k * 8 + t + 4];
            a[3] = smu[SP_ + (m0 + g + 8) * PSTR + k * 8 + t + 4];
            #pragma unroll
            for (int n = 0; n < 8; n++) {
                uint32_t b0 = smu[SV_ + (k * 8 + t)     * VSTR + n * 8 + g];
                uint32_t b1 = smu[SV_ + (k * 8 + t + 4) * VSTR + n * 8 + g];
                mma_tf32(Oacc[n], a, b0, b1);
            }
        }
    }

    // ---- epilogue: reduce rowsums within quad, normalize, store ----
    rsum0 += __shfl_xor_sync(0xffffffffu, rsum0, 1);
    rsum0 += __shfl_xor_sync(0xffffffffu, rsum0, 2);
    rsum1 += __shfl_xor_sync(0xffffffffu, rsum1, 1);
    rsum1 += __shfl_xor_sync(0xffffffffu, rsum1, 2);
    float inv0 = 1.0f / rsum0;
    float inv1 = 1.0f / rsum1;

    float* r0p = Og + (size_t)(row0 + m0 + g) * D_;
    float* r1p = Og + (size_t)(row0 + m0 + g + 8) * D_;
    #pragma unroll
    for (int n = 0; n < 8; n++) {
        float2 lo = { Oacc[n][0] * inv0, Oacc[n][1] * inv0 };
        float2 hi = { Oacc[n][2] * inv1, Oacc[n][3] * inv1 };
        *reinterpret_cast<float2*>(r0p + n * 8 + 2 * t) = lo;
        *reinterpret_cast<float2*>(r1p + n * 8 + 2 * t) = hi;
    }
}

// ---------------- 4-way projection GEMM (double-buffered SIMT) --------------
struct ProjArgs { const float* X; const float* W; const float* bias; float* out; };
struct ProjArgs4 { ProjArgs p[4]; };

__global__ __launch_bounds__(256) void proj_kernel(ProjArgs4 args)
{
    const ProjArgs pa = args.p[blockIdx.z];
    const float* __restrict__ X = pa.X;
    const float* __restrict__ W = pa.W;
    const float* __restrict__ bias = pa.bias;
    float* __restrict__ out = pa.out;

    __shared__ float As[2][8][128];
    __shared__ float Bs[2][8][128];
    const int tid  = threadIdx.x;
    const int row0 = blockIdx.y * 128;
    const int col0 = blockIdx.x * 128;
    const int aRow = tid >> 1;
    const int aCol = (tid & 1) * 4;
    const int bRow = tid >> 5;
    const int bCol = (tid & 31) * 4;
    const int tr = (tid >> 4) * 8;
    const int tc = (tid & 15) * 8;
    float acc[8][8] = {};

    const float* Aptr = X + (size_t)(row0 + aRow) * E_ + aCol;
    const float* Bptr = W + (size_t)bRow * E_ + col0 + bCol;

    {
        float4 a4 = *reinterpret_cast<const float4*>(Aptr);
        float4 b4 = *reinterpret_cast<const float4*>(Bptr);
        As[0][aCol + 0][aRow] = a4.x; As[0][aCol + 1][aRow] = a4.y;
        As[0][aCol + 2][aRow] = a4.z; As[0][aCol + 3][aRow] = a4.w;
        *reinterpret_cast<float4*>(&Bs[0][bRow][bCol]) = b4;
    }
    __syncthreads();

    int buf = 0;
    for (int k0 = 8; k0 <= E_; k0 += 8) {
        float4 na, nb;
        bool more = (k0 < E_);
        if (more) {
            na = *reinterpret_cast<const float4*>(Aptr + k0);
            nb = *reinterpret_cast<const float4*>(Bptr + (size_t)k0 * E_);
        }
        #pragma unroll
        for (int k = 0; k < 8; k++) {
            float ar[8], br[8];
            *reinterpret_cast<float4*>(ar)     = *reinterpret_cast<const float4*>(&As[buf][k][tr]);
            *reinterpret_cast<float4*>(ar + 4) = *reinterpret_cast<const float4*>(&As[buf][k][tr + 4]);
            *reinterpret_cast<float4*>(br)     = *reinterpret_cast<const float4*>(&Bs[buf][k][tc]);
            *reinterpret_cast<float4*>(br + 4) = *reinterpret_cast<const float4*>(&Bs[buf][k][tc + 4]);
            #pragma unroll
            for (int i = 0; i < 8; i++)
                #pragma unroll
                for (int j = 0; j < 8; j++)
                    acc[i][j] = fmaf(ar[i], br[j], acc[i][j]);
        }
        if (more) {
            int nb_ = buf ^ 1;
            As[nb_][aCol + 0][aRow] = na.x; As[nb_][aCol + 1][aRow] = na.y;
            As[nb_][aCol + 2][aRow] = na.z; As[nb_][aCol + 3][aRow] = na.w;
            *reinterpret_cast<float4*>(&Bs[nb_][bRow][bCol]) = nb;
        }
        __syncthreads();
        buf ^= 1;
    }

    #pragma unroll
    for (int i = 0; i < 8; i++) {
        int m  = row0 + tr + i;
        int b  = m >> 11;
        int ii = m & 2047;
        #pragma unroll
        for (int j = 0; j < 8; j++) {
            int c = col0 + tc + j;
            int h = c >> 6;
            int d = c & 63;
            out[(((size_t)b * H_ + h) * 2048 + ii) * D_ + d] = acc[i][j] + bias[c];
        }
    }
}

// ---------------- 2-way output projection (double-buffered SIMT) ------------
struct OutArgs { const float* ctx; const float* W; const float* bias; float* out; };
struct OutArgs2 { OutArgs p[2]; };

__global__ __launch_bounds__(256) void outproj_kernel(OutArgs2 args)
{
    const OutArgs pa = args.p[blockIdx.z];
    const float* __restrict__ ctx  = pa.ctx;
    const float* __restrict__ W    = pa.W;
    const float* __restrict__ bias = pa.bias;
    float* __restrict__ out = pa.out;

    __shared__ float As[2][8][128];
    __shared__ float Bs[2][8][128];
    const int tid  = threadIdx.x;
    const int row0 = blockIdx.y * 128;
    const int col0 = blockIdx.x * 128;
    const int aRow = tid >> 1;
    const int aCol = (tid & 1) * 4;
    const int bRow = tid >> 5;
    const int bCol = (tid & 31) * 4;
    const int tr = (tid >> 4) * 8;
    const int tc = (tid & 15) * 8;
    float acc[8][8] = {};

    const int m  = row0 + aRow;
    const int bb = m >> 11;
    const int ii = m & 2047;
    const float* Abase = ctx + ((size_t)bb * H_ * 2048 + ii) * D_;
    const float* Bptr  = W + (size_t)bRow * E_ + col0 + bCol;

    {
        int k = aCol;
        float4 a4 = *reinterpret_cast<const float4*>(Abase + (size_t)(k >> 6) * 2048 * D_ + (k & 63));
        float4 b4 = *reinterpret_cast<const float4*>(Bptr);
        As[0][aCol + 0][aRow] = a4.x; As[0][aCol + 1][aRow] = a4.y;
        As[0][aCol + 2][aRow] = a4.z; As[0][aCol + 3][aRow] = a4.w;
        *reinterpret_cast<float4*>(&Bs[0][bRow][bCol]) = b4;
    }
    __syncthreads();

    int buf = 0;
    for (int k0 = 8; k0 <= E_; k0 += 8) {
        float4 na, nb;
        bool more = (k0 < E_);
        if (more) {
            int k = k0 + aCol;
            na = *reinterpret_cast<const float4*>(Abase + (size_t)(k >> 6) * 2048 * D_ + (k & 63));
            nb = *reinterpret_cast<const float4*>(Bptr + (size_t)k0 * E_);
        }
        #pragma unroll
        for (int kk = 0; kk < 8; kk++) {
            float ar[8], br[8];
            *reinterpret_cast<float4*>(ar)     = *reinterpret_cast<const float4*>(&As[buf][kk][tr]);
            *reinterpret_cast<float4*>(ar + 4) = *reinterpret_cast<const float4*>(&As[buf][kk][tr + 4]);
            *reinterpret_cast<float4*>(br)     = *reinterpret_cast<const float4*>(&Bs[buf][kk][tc]);
            *reinterpret_cast<float4*>(br + 4) = *reinterpret_cast<const float4*>(&Bs[buf][kk][tc + 4]);
            #pragma unroll
            for (int i = 0; i < 8; i++)
                #pragma unroll
                for (int j = 0; j < 8; j++)
                    acc[i][j] = fmaf(ar[i], br[j], acc[i][j]);
        }
        if (more) {
            int nbuf = buf ^ 1;
            As[nbuf][aCol + 0][aRow] = na.x; As[nbuf][aCol + 1][aRow] = na.y;
            As[nbuf][aCol + 2][aRow] = na.z; As[nbuf][aCol + 3][aRow] = na.w;
            *reinterpret_cast<float4*>(&Bs[nbuf][bRow][bCol]) = nb;
        }
        __syncthreads();
        buf ^= 1;
    }

    #pragma unroll
    for (int i = 0; i < 8; i++) {
        size_t om = (size_t)(row0 + tr + i) * E_;
        #pragma unroll
        for (int j = 0; j < 8; j++) {
            int c = col0 + tc + j;
            out[om + c] = acc[i][j] + bias[c];
        }
    }
}

// ---------------------------------------------------------------------------
extern "C" void kernel_launch(void* const* d_in, const int* in_sizes, int n_in,
                              void* d_out, int out_size)
{
    (void)in_sizes; (void)n_in; (void)out_size;
    const float* a     = (const float*)d_in[0];
    const float* b     = (const float*)d_in[1];
    const float* Wa_qk = (const float*)d_in[2];
    const float* ba_qk = (const float*)d_in[3];
    const float* Wa_v  = (const float*)d_in[4];
    const float* ba_v  = (const float*)d_in[5];
    const float* Wb_qk = (const float*)d_in[6];
    const float* bb_qk = (const float*)d_in[7];
    const float* Wb_v  = (const float*)d_in[8];
    const float* bb_v  = (const float*)d_in[9];
    const float* Wa_o  = (const float*)d_in[10];
    const float* ba_o  = (const float*)d_in[11];
    const float* Wb_o  = (const float*)d_in[12];
    const float* bb_o  = (const float*)d_in[13];
    float* out = (float*)d_out;

    float* scratch = nullptr;
    cudaGetSymbolAddress((void**)&scratch, g_scratch);
    float* aq   = scratch + OFF_AQ;
    float* av   = scratch + OFF_AV;
    float* bq   = scratch + OFF_BQ;
    float* bv   = scratch + OFF_BV;
    float* actx = scratch + OFF_ACTX;
    float* bctx = scratch + OFF_BCTX;

    cudaFuncSetAttribute(flash_kernel, cudaFuncAttributeMaxDynamicSharedMemorySize, FLASH_SMEM);

    ProjArgs4 pargs;
    pargs.p[0] = { a, Wa_qk, ba_qk, aq };
    pargs.p[1] = { a, Wa_v,  ba_v,  av };
    pargs.p[2] = { b, Wb_qk, bb_qk, bq };
    pargs.p[3] = { b, Wb_v,  bb_v,  bv };
    proj_kernel<<<dim3(E_ / 128, (B_ * 2048) / 128, 4), 256>>>(pargs);

    flash_kernel<<<dim3(16, BH_, 2), 256, FLASH_SMEM>>>(aq, bq, av, bv, actx, bctx);

    OutArgs2 oargs;
    oargs.p[0] = { actx, Wa_o, ba_o, out };
    oargs.p[1] = { bctx, Wb_o, bb_o, out + (size_t)B_ * 2048 * E_ };
    outproj_kernel<<<dim3(E_ / 128, (B_ * 2048) / 128, 2), 256>>>(oargs);
}

// round 5
// speedup vs baseline: 2.6289x; 1.6918x over previous
#include <cuda_runtime.h>
#include <math.h>
#include <stdint.h>

#define B_    2
#define H_    16
#define E_    1024
#define D_    64
#define BH_   32
#define NSEQ  2048

// ---------------- scratch (floats) ------------------------------------------
static const size_t OFF_AQ   = 0;
static const size_t OFF_AV   = OFF_AQ  + 4194304;
static const size_t OFF_BQ   = OFF_AV  + 4194304;
static const size_t OFF_BV   = OFF_BQ  + 4194304;
static const size_t OFF_ACTX = OFF_BV  + 4194304;
static const size_t OFF_BCTX = OFF_ACTX+ 4194304;
static const size_t OFF_AT   = OFF_BCTX+ 4194304;   // tf32-rounded a
static const size_t OFF_BT   = OFF_AT  + 4194304;   // tf32-rounded b
static const size_t OFF_W    = OFF_BT  + 4194304;   // 6 tf32-rounded weights
static const size_t SCRATCH_ELEMS = OFF_W + 6 * 1048576;

__device__ float g_scratch[SCRATCH_ELEMS];

// ---------------- fast exp on FMA pipe --------------------------------------
__device__ __forceinline__ float fexp(float x) {
    const float L2E = 1.4426950408889634f;
    const float LN2 = 0.6931471805599453f;
    float t = x * L2E;
    float r = rintf(t);
    float y = fmaf(-r, LN2, x);
    float p = 8.3333333e-3f;
    p = fmaf(p, y, 4.1666667e-2f);
    p = fmaf(p, y, 1.6666667e-1f);
    p = fmaf(p, y, 0.5f);
    p = fmaf(p, y, 1.0f);
    p = fmaf(p, y, 1.0f);
    int e = (((int)r) + 127) << 23;
    return p * __int_as_float(e);
}

__device__ __forceinline__ uint32_t to_tf32(float f) {
    uint32_t r;
    asm("cvt.rna.tf32.f32 %0, %1;" : "=r"(r) : "f"(f));
    return r;
}

__device__ __forceinline__ uint32_t smem_u32(const void* p) {
    uint32_t a;
    asm("{ .reg .u64 t; cvta.to.shared.u64 t, %1; cvt.u32.u64 %0, t; }" : "=r"(a) : "l"(p));
    return a;
}

// mma.sync m16n8k8 tf32 (portable PTX)
__device__ __forceinline__ void mma_tf32(float c[4], const uint32_t a[4],
                                         uint32_t b0, uint32_t b1) {
    asm volatile(
        "mma.sync.aligned.m16n8k8.row.col.f32.tf32.tf32.f32 "
        "{%0,%1,%2,%3}, {%4,%5,%6,%7}, {%8,%9}, {%0,%1,%2,%3};"
        : "+f"(c[0]), "+f"(c[1]), "+f"(c[2]), "+f"(c[3])
        : "r"(a[0]), "r"(a[1]), "r"(a[2]), "r"(a[3]), "r"(b0), "r"(b1));
}

__device__ __forceinline__ void cp16(uint32_t dst, const void* src) {
    asm volatile("cp.async.cg.shared.global [%0], [%1], 16;" :: "r"(dst), "l"(src) : "memory");
}
#define CP_COMMIT() asm volatile("cp.async.commit_group;" ::: "memory")
#define CP_WAIT(n)  asm volatile("cp.async.wait_group %0;" :: "n"(n) : "memory")

// ---------------- tf32 pre-rounding pass -------------------------------------
__global__ void cvt_kernel(const float4* __restrict__ src, float4* __restrict__ dst, int n4) {
    int i = blockIdx.x * blockDim.x + threadIdx.x;
    int stride = gridDim.x * blockDim.x;
    for (; i < n4; i += stride) {
        float4 v = src[i];
        float4 o;
        o.x = __uint_as_float(to_tf32(v.x));
        o.y = __uint_as_float(to_tf32(v.y));
        o.z = __uint_as_float(to_tf32(v.z));
        o.w = __uint_as_float(to_tf32(v.w));
        dst[i] = o;
    }
}

// ================= tf32 MMA GEMM kernels =====================================
// Tile 128x128x32; 8 warps (4m x 2n); warp tile 32x64; strides 36/132 so all
// fragment LDS patterns are bank-conflict-free. cp.async double-buffered.
#define PAK  36
#define PBK  132
#define PA_FLTS (128*PAK)                 // 4608 per buffer
#define PB_FLTS (32*PBK)                  // 4224 per buffer
#define PB_OFF  (2*PA_FLTS)               // 9216
#define PROJ_SMEM ((PB_OFF + 2*PB_FLTS)*4)  // 70656 bytes

struct ProjArgs { const float* X; const float* W; const float* bias; float* out; };
struct ProjArgs4 { ProjArgs p[4]; };
struct OutArgs { const float* ctx; const float* W; const float* bias; float* out; };
struct OutArgs2 { OutArgs p[2]; };

// proj: X[4096,1024] @ W[1024,1024] + bias -> head layout [B,H,2048,D]
__global__ __launch_bounds__(256, 2) void projmma_kernel(ProjArgs4 args)
{
    const ProjArgs pa = args.p[blockIdx.z];
    const float* __restrict__ X = pa.X;
    const float* __restrict__ W = pa.W;

    extern __shared__ float sm[];
    uint32_t* smu = reinterpret_cast<uint32_t*>(sm);
    const uint32_t smb = smem_u32(sm);

    const int tid  = threadIdx.x;
    const int lane = tid & 31;
    const int warp = tid >> 5;
    const int g = lane >> 2, t = lane & 3;
    const int wm = warp & 3, wn = warp >> 2;
    const int row0 = blockIdx.y * 128;
    const int col0 = blockIdx.x * 128;

    const int ar = tid >> 3;          // 0..31 (A rows, 4 passes)
    const int ak = (tid & 7) * 4;     // A k-chunk
    const int brr = tid >> 5;         // 0..7  (B rows, 4 passes)
    const int bc = (tid & 31) * 4;    // B col-chunk

    float acc[2][8][4];
    #pragma unroll
    for (int i = 0; i < 2; i++)
        #pragma unroll
        for (int n = 0; n < 8; n++)
            #pragma unroll
            for (int j = 0; j < 4; j++) acc[i][n][j] = 0.0f;

    // prefetch tile 0
    #pragma unroll
    for (int p = 0; p < 4; p++) {
        int r = ar + p * 32;
        cp16(smb + (uint32_t)(r * PAK + ak) * 4, X + (size_t)(row0 + r) * E_ + ak);
    }
    #pragma unroll
    for (int p = 0; p < 4; p++) {
        int r = brr + p * 8;
        cp16(smb + (uint32_t)(PB_OFF + r * PBK + bc) * 4, W + (size_t)r * E_ + col0 + bc);
    }
    CP_COMMIT();

    int buf = 0;
    for (int kt = 0; kt < 32; kt++) {
        __syncthreads();   // everyone done reading buf^1 from iteration kt-1
        if (kt + 1 < 32) {
            int k0 = (kt + 1) * 32;
            int nb = buf ^ 1;
            #pragma unroll
            for (int p = 0; p < 4; p++) {
                int r = ar + p * 32;
                cp16(smb + (uint32_t)(nb * PA_FLTS + r * PAK + ak) * 4,
                     X + (size_t)(row0 + r) * E_ + k0 + ak);
            }
            #pragma unroll
            for (int p = 0; p < 4; p++) {
                int r = brr + p * 8;
                cp16(smb + (uint32_t)(PB_OFF + nb * PB_FLTS + r * PBK + bc) * 4,
                     W + (size_t)(k0 + r) * E_ + col0 + bc);
            }
            CP_COMMIT();
            CP_WAIT(1);
        } else {
            CP_WAIT(0);
        }
        __syncthreads();

        const uint32_t* A  = smu + buf * PA_FLTS;
        const uint32_t* Bm = smu + PB_OFF + buf * PB_FLTS;
        #pragma unroll
        for (int ks = 0; ks < 4; ks++) {
            const int kk = ks * 8 + t;
            uint32_t af[2][4];
            #pragma unroll
            for (int i = 0; i < 2; i++) {
                int mb = wm * 32 + i * 16;
                af[i][0] = A[(mb + g) * PAK + kk];
                af[i][1] = A[(mb + g + 8) * PAK + kk];
                af[i][2] = A[(mb + g) * PAK + kk + 4];
                af[i][3] = A[(mb + g + 8) * PAK + kk + 4];
            }
            uint32_t bf[8][2];
            #pragma unroll
            for (int n = 0; n < 8; n++) {
                bf[n][0] = Bm[kk * PBK + wn * 64 + n * 8 + g];
                bf[n][1] = Bm[(kk + 4) * PBK + wn * 64 + n * 8 + g];
            }
            #pragma unroll
            for (int i = 0; i < 2; i++)
                #pragma unroll
                for (int n = 0; n < 8; n++)
                    mma_tf32(acc[i][n], af[i], bf[n][0], bf[n][1]);
        }
        buf ^= 1;
    }

    // epilogue: bias + scatter to head layout
    const int hbase = col0 + wn * 64;
    const int h = hbase >> 6;
    #pragma unroll
    for (int i = 0; i < 2; i++) {
        int m = row0 + wm * 32 + i * 16;
        int bb = m >> 11;
        int ii = m & 2047;
        float* base = pa.out + (((size_t)bb * H_ + h) * NSEQ) * D_;
        #pragma unroll
        for (int n = 0; n < 8; n++) {
            int d = n * 8 + 2 * t;
            float2 bi = *reinterpret_cast<const float2*>(pa.bias + hbase + d);
            float2 lo = { acc[i][n][0] + bi.x, acc[i][n][1] + bi.y };
            float2 hi = { acc[i][n][2] + bi.x, acc[i][n][3] + bi.y };
            *reinterpret_cast<float2*>(base + (size_t)(ii + g) * D_ + d) = lo;
            *reinterpret_cast<float2*>(base + (size_t)(ii + g + 8) * D_ + d) = hi;
        }
    }
}

// outproj: gather(ctx head layout) @ W + bias -> row-major [4096,1024]
__global__ __launch_bounds__(256, 2) void outmma_kernel(OutArgs2 args)
{
    const OutArgs pa = args.p[blockIdx.z];
    const float* __restrict__ C = pa.ctx;
    const float* __restrict__ W = pa.W;

    extern __shared__ float sm[];
    uint32_t* smu = reinterpret_cast<uint32_t*>(sm);
    const uint32_t smb = smem_u32(sm);

    const int tid  = threadIdx.x;
    const int lane = tid & 31;
    const int warp = tid >> 5;
    const int g = lane >> 2, t = lane & 3;
    const int wm = warp & 3, wn = warp >> 2;
    const int row0 = blockIdx.y * 128;
    const int col0 = blockIdx.x * 128;

    const int ar = tid >> 3;
    const int ak = (tid & 7) * 4;
    const int brr = tid >> 5;
    const int bc = (tid & 31) * 4;

    float acc[2][8][4];
    #pragma unroll
    for (int i = 0; i < 2; i++)
        #pragma unroll
        for (int n = 0; n < 8; n++)
            #pragma unroll
            for (int j = 0; j < 4; j++) acc[i][n][j] = 0.0f;

    // A source addressing (gather from head layout)
    auto asrc = [&](int r, int k) -> const float* {
        int m = row0 + r;
        int bb = m >> 11, ii = m & 2047;
        int h = k >> 6, d = k & 63;
        return C + (((size_t)bb * H_ + h) * NSEQ + ii) * D_ + d;
    };

    #pragma unroll
    for (int p = 0; p < 4; p++) {
        int r = ar + p * 32;
        cp16(smb + (uint32_t)(r * PAK + ak) * 4, asrc(r, ak));
    }
    #pragma unroll
    for (int p = 0; p < 4; p++) {
        int r = brr + p * 8;
        cp16(smb + (uint32_t)(PB_OFF + r * PBK + bc) * 4, W + (size_t)r * E_ + col0 + bc);
    }
    CP_COMMIT();

    int buf = 0;
    for (int kt = 0; kt < 32; kt++) {
        __syncthreads();
        if (kt + 1 < 32) {
            int k0 = (kt + 1) * 32;
            int nb = buf ^ 1;
            #pragma unroll
            for (int p = 0; p < 4; p++) {
                int r = ar + p * 32;
                cp16(smb + (uint32_t)(nb * PA_FLTS + r * PAK + ak) * 4, asrc(r, k0 + ak));
            }
            #pragma unroll
            for (int p = 0; p < 4; p++) {
                int r = brr + p * 8;
                cp16(smb + (uint32_t)(PB_OFF + nb * PB_FLTS + r * PBK + bc) * 4,
                     W + (size_t)(k0 + r) * E_ + col0 + bc);
            }
            CP_COMMIT();
            CP_WAIT(1);
        } else {
            CP_WAIT(0);
        }
        __syncthreads();

        const uint32_t* A  = smu + buf * PA_FLTS;
        const uint32_t* Bm = smu + PB_OFF + buf * PB_FLTS;
        #pragma unroll
        for (int ks = 0; ks < 4; ks++) {
            const int kk = ks * 8 + t;
            uint32_t af[2][4];
            #pragma unroll
            for (int i = 0; i < 2; i++) {
                int mb = wm * 32 + i * 16;
                af[i][0] = A[(mb + g) * PAK + kk];
                af[i][1] = A[(mb + g + 8) * PAK + kk];
                af[i][2] = A[(mb + g) * PAK + kk + 4];
                af[i][3] = A[(mb + g + 8) * PAK + kk + 4];
            }
            uint32_t bf[8][2];
            #pragma unroll
            for (int n = 0; n < 8; n++) {
                bf[n][0] = Bm[kk * PBK + wn * 64 + n * 8 + g];
                bf[n][1] = Bm[(kk + 4) * PBK + wn * 64 + n * 8 + g];
            }
            #pragma unroll
            for (int i = 0; i < 2; i++)
                #pragma unroll
                for (int n = 0; n < 8; n++)
                    mma_tf32(acc[i][n], af[i], bf[n][0], bf[n][1]);
        }
        buf ^= 1;
    }

    // epilogue: bias + row-major store
    #pragma unroll
    for (int i = 0; i < 2; i++) {
        int m = row0 + wm * 32 + i * 16;
        #pragma unroll
        for (int n = 0; n < 8; n++) {
            int c = col0 + wn * 64 + n * 8 + 2 * t;
            float2 bi = *reinterpret_cast<const float2*>(pa.bias + c);
            float2 lo = { acc[i][n][0] + bi.x, acc[i][n][1] + bi.y };
            float2 hi = { acc[i][n][2] + bi.x, acc[i][n][3] + bi.y };
            *reinterpret_cast<float2*>(pa.out + (size_t)(m + g) * E_ + c) = lo;
            *reinterpret_cast<float2*>(pa.out + (size_t)(m + g + 8) * E_ + c) = hi;
        }
    }
}

// ================= fused flash kernel (unchanged core) =======================
#define QSTR 68
#define KSTR 68
#define VSTR 72
#define PSTR 132
#define SQ_  0
#define SK_  (SQ_ + 128*QSTR)
#define SV_  (SK_ + 128*KSTR)
#define SP_  (SV_ + 128*VSTR)
#define FLASH_FLOATS (SP_ + 128*PSTR)
#define FLASH_SMEM   (FLASH_FLOATS*4)

__global__ __launch_bounds__(256) void flash_kernel(
    const float* __restrict__ aq, const float* __restrict__ bq,
    const float* __restrict__ av, const float* __restrict__ bv,
    float* __restrict__ actx, float* __restrict__ bctx)
{
    extern __shared__ float sm[];
    uint32_t* smu = reinterpret_cast<uint32_t*>(sm);

    const int tid  = threadIdx.x;
    const int lane = tid & 31;
    const int warp = tid >> 5;
    const int g = lane >> 2;
    const int t = lane & 3;
    const int m0 = warp * 16;

    const int side = blockIdx.z;
    const int bh   = blockIdx.y;
    const int row0 = blockIdx.x * 128;

    const float* Qg = (side ? bq : aq) + (size_t)bh * NSEQ * D_;
    const float* Kg = (side ? aq : bq) + (size_t)bh * NSEQ * D_;
    const float* Vg = (side ? av : bv) + (size_t)bh * NSEQ * D_;
    float* Og = (side ? bctx : actx) + (size_t)bh * NSEQ * D_;

    {
        const float4* src = reinterpret_cast<const float4*>(Qg + (size_t)row0 * D_);
        #pragma unroll
        for (int i = 0; i < 8; i++) {
            int gi = i * 1024 + tid * 4;
            float4 v = src[gi >> 2];
            int r = gi >> 6, c = gi & 63;
            uint4 u = { to_tf32(v.x), to_tf32(v.y), to_tf32(v.z), to_tf32(v.w) };
            *reinterpret_cast<uint4*>(&smu[SQ_ + r * QSTR + c]) = u;
        }
    }
    __syncthreads();

    uint32_t Qf[8][4];
    #pragma unroll
    for (int k = 0; k < 8; k++) {
        Qf[k][0] = smu[SQ_ + (m0 + g)     * QSTR + k * 8 + t];
        Qf[k][1] = smu[SQ_ + (m0 + g + 8) * QSTR + k * 8 + t];
        Qf[k][2] = smu[SQ_ + (m0 + g)     * QSTR + k * 8 + t + 4];
        Qf[k][3] = smu[SQ_ + (m0 + g + 8) * QSTR + k * 8 + t + 4];
    }

    float Oacc[8][4];
    #pragma unroll
    for (int n = 0; n < 8; n++)
        #pragma unroll
        for (int j = 0; j < 4; j++) Oacc[n][j] = 0.0f;
    float rsum0 = 0.0f, rsum1 = 0.0f;

    for (int kt = 0; kt < 16; kt++) {
        const int key0 = kt * 128;
        if (kt > 0) __syncthreads();

        {
            const float4* ks = reinterpret_cast<const float4*>(Kg + (size_t)key0 * D_);
            const float4* vs = reinterpret_cast<const float4*>(Vg + (size_t)key0 * D_);
            #pragma unroll
            for (int i = 0; i < 8; i++) {
                int gi = i * 1024 + tid * 4;
                int r = gi >> 6, c = gi & 63;
                float4 kv = ks[gi >> 2];
                uint4 ku = { to_tf32(kv.x), to_tf32(kv.y), to_tf32(kv.z), to_tf32(kv.w) };
                *reinterpret_cast<uint4*>(&smu[SK_ + r * KSTR + c]) = ku;
                float4 vv = vs[gi >> 2];
                uint4 vu = { to_tf32(vv.x), to_tf32(vv.y), to_tf32(vv.z), to_tf32(vv.w) };
                *reinterpret_cast<uint4*>(&smu[SV_ + r * VSTR + c]) = vu;
            }
        }
        __syncthreads();

        #pragma unroll
        for (int n = 0; n < 16; n++) {
            float c4[4] = {0.0f, 0.0f, 0.0f, 0.0f};
            #pragma unroll
            for (int k = 0; k < 8; k++) {
                uint32_t b0 = smu[SK_ + (n * 8 + g) * KSTR + k * 8 + t];
                uint32_t b1 = smu[SK_ + (n * 8 + g) * KSTR + k * 8 + t + 4];
                mma_tf32(c4, Qf[k], b0, b1);
            }
            float e0 = fexp(c4[0] * 0.125f);
            float e1 = fexp(c4[1] * 0.125f);
            float e2 = fexp(c4[2] * 0.125f);
            float e3 = fexp(c4[3] * 0.125f);
            rsum0 += e0 + e1;
            rsum1 += e2 + e3;
            uint2 lo = { to_tf32(e0), to_tf32(e1) };
            uint2 hi = { to_tf32(e2), to_tf32(e3) };
            *reinterpret_cast<uint2*>(&smu[SP_ + (m0 + g)     * PSTR + n * 8 + 2 * t]) = lo;
            *reinterpret_cast<uint2*>(&smu[SP_ + (m0 + g + 8) * PSTR + n * 8 + 2 * t]) = hi;
        }
        __syncwarp();

        #pragma unroll
        for (int k = 0; k < 16; k++) {
            uint32_t a[4];
            a[0] = smu[SP_ + (m0 + g)     * PSTR + k * 8 + t];
            a[1] = smu[SP_ + (m0 + g + 8) * PSTR + k * 8 + t];
            a[2] = smu[SP_ + (m0 + g)     * PSTR + k * 8 + t + 4];
            a[3] = smu[SP_ + (m0 + g + 8) * PSTR + k * 8 + t + 4];
            #pragma unroll
            for (int n = 0; n < 8; n++) {
                uint32_t b0 = smu[SV_ + (k * 8 + t)     * VSTR + n * 8 + g];
                uint32_t b1 = smu[SV_ + (k * 8 + t + 4) * VSTR + n * 8 + g];
                mma_tf32(Oacc[n], a, b0, b1);
            }
        }
    }

    rsum0 += __shfl_xor_sync(0xffffffffu, rsum0, 1);
    rsum0 += __shfl_xor_sync(0xffffffffu, rsum0, 2);
    rsum1 += __shfl_xor_sync(0xffffffffu, rsum1, 1);
    rsum1 += __shfl_xor_sync(0xffffffffu, rsum1, 2);
    float inv0 = 1.0f / rsum0;
    float inv1 = 1.0f / rsum1;

    // store ctx tf32-rounded so outproj can cp.async it losslessly
    float* r0p = Og + (size_t)(row0 + m0 + g) * D_;
    float* r1p = Og + (size_t)(row0 + m0 + g + 8) * D_;
    #pragma unroll
    for (int n = 0; n < 8; n++) {
        float2 lo = { __uint_as_float(to_tf32(Oacc[n][0] * inv0)),
                      __uint_as_float(to_tf32(Oacc[n][1] * inv0)) };
        float2 hi = { __uint_as_float(to_tf32(Oacc[n][2] * inv1)),
                      __uint_as_float(to_tf32(Oacc[n][3] * inv1)) };
        *reinterpret_cast<float2*>(r0p + n * 8 + 2 * t) = lo;
        *reinterpret_cast<float2*>(r1p + n * 8 + 2 * t) = hi;
    }
}

// ---------------------------------------------------------------------------
extern "C" void kernel_launch(void* const* d_in, const int* in_sizes, int n_in,
                              void* d_out, int out_size)
{
    (void)in_sizes; (void)n_in; (void)out_size;
    const float* a     = (const float*)d_in[0];
    const float* b     = (const float*)d_in[1];
    const float* Wa_qk = (const float*)d_in[2];
    const float* ba_qk = (const float*)d_in[3];
    const float* Wa_v  = (const float*)d_in[4];
    const float* ba_v  = (const float*)d_in[5];
    const float* Wb_qk = (const float*)d_in[6];
    const float* bb_qk = (const float*)d_in[7];
    const float* Wb_v  = (const float*)d_in[8];
    const float* bb_v  = (const float*)d_in[9];
    const float* Wa_o  = (const float*)d_in[10];
    const float* ba_o  = (const float*)d_in[11];
    const float* Wb_o  = (const float*)d_in[12];
    const float* bb_o  = (const float*)d_in[13];
    float* out = (float*)d_out;

    float* scratch = nullptr;
    cudaGetSymbolAddress((void**)&scratch, g_scratch);
    float* aq   = scratch + OFF_AQ;
    float* av   = scratch + OFF_AV;
    float* bq   = scratch + OFF_BQ;
    float* bv   = scratch + OFF_BV;
    float* actx = scratch + OFF_ACTX;
    float* bctx = scratch + OFF_BCTX;
    float* aT   = scratch + OFF_AT;
    float* bT   = scratch + OFF_BT;
    float* wT   = scratch + OFF_W;   // 6 x 1M: Wa_qk, Wa_v, Wb_qk, Wb_v, Wa_o, Wb_o

    cudaFuncSetAttribute(flash_kernel,   cudaFuncAttributeMaxDynamicSharedMemorySize, FLASH_SMEM);
    cudaFuncSetAttribute(projmma_kernel, cudaFuncAttributeMaxDynamicSharedMemorySize, PROJ_SMEM);
    cudaFuncSetAttribute(outmma_kernel,  cudaFuncAttributeMaxDynamicSharedMemorySize, PROJ_SMEM);

    // tf32 pre-rounding (makes cp.async GEMM operands tf32-exact)
    cvt_kernel<<<1024, 256>>>((const float4*)a, (float4*)aT, 1048576);
    cvt_kernel<<<1024, 256>>>((const float4*)b, (float4*)bT, 1048576);
    cvt_kernel<<<512, 256>>>((const float4*)Wa_qk, (float4*)(wT + 0 * 1048576), 262144);
    cvt_kernel<<<512, 256>>>((const float4*)Wa_v,  (float4*)(wT + 1 * 1048576), 262144);
    cvt_kernel<<<512, 256>>>((const float4*)Wb_qk, (float4*)(wT + 2 * 1048576), 262144);
    cvt_kernel<<<512, 256>>>((const float4*)Wb_v,  (float4*)(wT + 3 * 1048576), 262144);
    cvt_kernel<<<512, 256>>>((const float4*)Wa_o,  (float4*)(wT + 4 * 1048576), 262144);
    cvt_kernel<<<512, 256>>>((const float4*)Wb_o,  (float4*)(wT + 5 * 1048576), 262144);

    ProjArgs4 pargs;
    pargs.p[0] = { aT, wT + 0 * 1048576, ba_qk, aq };
    pargs.p[1] = { aT, wT + 1 * 1048576, ba_v,  av };
    pargs.p[2] = { bT, wT + 2 * 1048576, bb_qk, bq };
    pargs.p[3] = { bT, wT + 3 * 1048576, bb_v,  bv };
    projmma_kernel<<<dim3(E_ / 128, (B_ * NSEQ) / 128, 4), 256, PROJ_SMEM>>>(pargs);

    flash_kernel<<<dim3(16, BH_, 2), 256, FLASH_SMEM>>>(aq, bq, av, bv, actx, bctx);

    OutArgs2 oargs;
    oargs.p[0] = { actx, wT + 4 * 1048576, ba_o, out };
    oargs.p[1] = { bctx, wT + 5 * 1048576, bb_o, out + (size_t)B_ * NSEQ * E_ };
    outmma_kernel<<<dim3(E_ / 128, (B_ * NSEQ) / 128, 2), 256, PROJ_SMEM>>>(oargs);
}

// round 6
// speedup vs baseline: 4.7607x; 1.8109x over previous
#include <cuda_runtime.h>
#include <cuda_fp16.h>
#include <math.h>
#include <stdint.h>

#define B_    2
#define H_    16
#define E_    1024
#define D_    64
#define BH_   32
#define NSEQ  2048

// ---------------- scratch (float units; halves live inside) ------------------
static const size_t OFF_AQ   = 0;                   // half [32][2048][64]
static const size_t OFF_BQ   = OFF_AQ   + 2097152;
static const size_t OFF_AVT  = OFF_BQ   + 2097152;  // half [32][64][2048] (transposed V)
static const size_t OFF_BVT  = OFF_AVT  + 2097152;
static const size_t OFF_ACTX = OFF_BVT  + 2097152;  // half [32][2048][64]
static const size_t OFF_BCTX = OFF_ACTX + 2097152;
static const size_t OFF_ATH  = OFF_BCTX + 2097152;  // half [4096][1024]
static const size_t OFF_BTH  = OFF_ATH  + 2097152;
static const size_t OFF_WT   = OFF_BTH  + 2097152;  // 6x half [1024n][1024k] (transposed)
static const size_t SCRATCH_ELEMS = OFF_WT + 6 * 524288;
__device__ float g_scratch[SCRATCH_ELEMS];

// ---------------- helpers ----------------------------------------------------
__device__ __forceinline__ float fexp(float x) {
    const float L2E = 1.4426950408889634f;
    const float LN2 = 0.6931471805599453f;
    float t = x * L2E;
    float r = rintf(t);
    float y = fmaf(-r, LN2, x);
    float p = 8.3333333e-3f;
    p = fmaf(p, y, 4.1666667e-2f);
    p = fmaf(p, y, 1.6666667e-1f);
    p = fmaf(p, y, 0.5f);
    p = fmaf(p, y, 1.0f);
    p = fmaf(p, y, 1.0f);
    int e = (((int)r) + 127) << 23;
    return p * __int_as_float(e);
}

__device__ __forceinline__ uint32_t pack_h2(float lo, float hi) {
    __half2 h = __floats2half2_rn(lo, hi);
    return *reinterpret_cast<uint32_t*>(&h);
}

__device__ __forceinline__ uint32_t smem_u32(const void* p) {
    uint32_t a;
    asm("{ .reg .u64 t; cvta.to.shared.u64 t, %1; cvt.u32.u64 %0, t; }" : "=r"(a) : "l"(p));
    return a;
}

// fp16 mma m16n8k16 with fp32 accumulate (portable PTX, sm_80+)
__device__ __forceinline__ void mma_h(float c[4], const uint32_t a[4],
                                      uint32_t b0, uint32_t b1) {
    asm volatile(
        "mma.sync.aligned.m16n8k16.row.col.f32.f16.f16.f32 "
        "{%0,%1,%2,%3}, {%4,%5,%6,%7}, {%8,%9}, {%0,%1,%2,%3};"
        : "+f"(c[0]), "+f"(c[1]), "+f"(c[2]), "+f"(c[3])
        : "r"(a[0]), "r"(a[1]), "r"(a[2]), "r"(a[3]), "r"(b0), "r"(b1));
}

__device__ __forceinline__ void cp16(uint32_t dst, const void* src) {
    asm volatile("cp.async.cg.shared.global [%0], [%1], 16;" :: "r"(dst), "l"(src) : "memory");
}
#define CP_COMMIT() asm volatile("cp.async.commit_group;" ::: "memory")
#define CP_WAIT0()  asm volatile("cp.async.wait_group 0;" ::: "memory")

// ---------------- fp32 -> fp16 convert ---------------------------------------
__global__ void cvth_kernel(const float4* __restrict__ src, uint2* __restrict__ dst, int n4) {
    int i = blockIdx.x * blockDim.x + threadIdx.x;
    int stride = gridDim.x * blockDim.x;
    for (; i < n4; i += stride) {
        float4 v = src[i];
        uint2 o;
        o.x = pack_h2(v.x, v.y);
        o.y = pack_h2(v.z, v.w);
        dst[i] = o;
    }
}

// ---------------- weight transpose + convert: W[k][n] -> Wt[n][k] fp16 -------
__global__ __launch_bounds__(256) void wtrans_kernel(const float* __restrict__ W,
                                                     __half* __restrict__ Wt) {
    __shared__ float tile[32][33];
    const int n0 = blockIdx.x * 32, k0 = blockIdx.y * 32;
    const int tx = threadIdx.x & 31, ty = threadIdx.x >> 5;
    #pragma unroll
    for (int j = 0; j < 4; j++)
        tile[ty + 8 * j][tx] = W[(size_t)(k0 + ty + 8 * j) * E_ + n0 + tx];
    __syncthreads();
    #pragma unroll
    for (int j = 0; j < 4; j++)
        Wt[(size_t)(n0 + ty + 8 * j) * E_ + k0 + tx] = __float2half_rn(tile[tx][ty + 8 * j]);
}

// ================= fp16 projection GEMM =======================================
// 128x128x64 tiles, 8 warps (4m x 2n), warp 32x64. A[m][k], B=Wt[n][k] fp16.
// smem word stride 36 (= 32 data words + 4 pad) -> conflict-free fragments.
#define GW 36
#define GA_WORDS (128*GW)              // 4608 words per buffer
#define GB_BASE  (2*GA_WORDS)
#define GEMM_SMEM (4*GA_WORDS*4)       // 73728 bytes

struct PArgs { const __half* X; const __half* Wt; const float* bias; __half* out; int vmode; };
struct PArgs4 { PArgs p[4]; };
struct OArgs { const __half* ctx; const __half* Wt; const float* bias; float* out; };
struct OArgs2 { OArgs p[2]; };

__global__ __launch_bounds__(256, 2) void projh_kernel(PArgs4 args)
{
    const PArgs pa = args.p[blockIdx.z];
    extern __shared__ uint32_t smw[];
    const uint32_t smb = smem_u32(smw);

    const int tid  = threadIdx.x;
    const int lane = tid & 31;
    const int warp = tid >> 5;
    const int g = lane >> 2, t = lane & 3;
    const int wm = warp & 3, wn = warp >> 2;
    const int row0 = blockIdx.y * 128;
    const int col0 = blockIdx.x * 128;

    float acc[2][8][4];
    #pragma unroll
    for (int i = 0; i < 2; i++)
        #pragma unroll
        for (int n = 0; n < 8; n++)
            #pragma unroll
            for (int j = 0; j < 4; j++) acc[i][n][j] = 0.0f;

    // prefetch k-tile 0: A rows [row0..row0+128), B rows Wt[col0..col0+128), 64 halfs each
    #pragma unroll
    for (int p = 0; p < 4; p++) {
        int idx = p * 256 + tid, r = idx >> 3, c = idx & 7;
        cp16(smb + (uint32_t)(r * GW + c * 4) * 4, pa.X + (size_t)(row0 + r) * E_ + c * 8);
    }
    #pragma unroll
    for (int p = 0; p < 4; p++) {
        int idx = p * 256 + tid, r = idx >> 3, c = idx & 7;
        cp16(smb + (uint32_t)(GB_BASE + r * GW + c * 4) * 4, pa.Wt + (size_t)(col0 + r) * E_ + c * 8);
    }
    CP_COMMIT();

    int buf = 0;
    for (int kt = 0; kt < 16; kt++) {
        CP_WAIT0();
        __syncthreads();
        if (kt < 15) {
            int k0 = (kt + 1) * 64;
            int nb = buf ^ 1;
            #pragma unroll
            for (int p = 0; p < 4; p++) {
                int idx = p * 256 + tid, r = idx >> 3, c = idx & 7;
                cp16(smb + (uint32_t)(nb * GA_WORDS + r * GW + c * 4) * 4,
                     pa.X + (size_t)(row0 + r) * E_ + k0 + c * 8);
            }
            #pragma unroll
            for (int p = 0; p < 4; p++) {
                int idx = p * 256 + tid, r = idx >> 3, c = idx & 7;
                cp16(smb + (uint32_t)(GB_BASE + nb * GA_WORDS + r * GW + c * 4) * 4,
                     pa.Wt + (size_t)(col0 + r) * E_ + k0 + c * 8);
            }
            CP_COMMIT();
        }
        const uint32_t* A  = smw + buf * GA_WORDS;
        const uint32_t* Bm = smw + GB_BASE + buf * GA_WORDS;
        #pragma unroll
        for (int kk = 0; kk < 4; kk++) {
            uint32_t af[2][4];
            #pragma unroll
            for (int i = 0; i < 2; i++) {
                int mb = wm * 32 + i * 16;
                af[i][0] = A[(mb + g) * GW + kk * 8 + t];
                af[i][1] = A[(mb + g + 8) * GW + kk * 8 + t];
                af[i][2] = A[(mb + g) * GW + kk * 8 + t + 4];
                af[i][3] = A[(mb + g + 8) * GW + kk * 8 + t + 4];
            }
            uint32_t bf[8][2];
            #pragma unroll
            for (int n = 0; n < 8; n++) {
                bf[n][0] = Bm[(wn * 64 + n * 8 + g) * GW + kk * 8 + t];
                bf[n][1] = Bm[(wn * 64 + n * 8 + g) * GW + kk * 8 + t + 4];
            }
            #pragma unroll
            for (int i = 0; i < 2; i++)
                #pragma unroll
                for (int n = 0; n < 8; n++)
                    mma_h(acc[i][n], af[i], bf[n][0], bf[n][1]);
        }
        buf ^= 1;
    }

    // epilogue
    if (!pa.vmode) {
        // qk: half [bh][seq][64]
        #pragma unroll
        for (int i = 0; i < 2; i++) {
            int m = row0 + wm * 32 + i * 16;
            int bb = m >> 11, ii = m & 2047;
            #pragma unroll
            for (int n = 0; n < 8; n++) {
                int col = col0 + wn * 64 + n * 8 + 2 * t;
                int h = col >> 6, d = col & 63;
                float2 bi = *reinterpret_cast<const float2*>(pa.bias + col);
                __half* base = pa.out + ((size_t)(bb * H_ + h) * NSEQ) * D_ + d;
                *reinterpret_cast<uint32_t*>(base + (size_t)(ii + g) * D_) =
                    pack_h2(acc[i][n][0] + bi.x, acc[i][n][1] + bi.y);
                *reinterpret_cast<uint32_t*>(base + (size_t)(ii + g + 8) * D_) =
                    pack_h2(acc[i][n][2] + bi.x, acc[i][n][3] + bi.y);
            }
        }
    } else {
        // v: transposed half [bh][64][seq]
        #pragma unroll
        for (int i = 0; i < 2; i++) {
            int m = row0 + wm * 32 + i * 16;
            int bb = m >> 11, ii = m & 2047;
            #pragma unroll
            for (int n = 0; n < 8; n++) {
                int col = col0 + wn * 64 + n * 8 + 2 * t;
                int h = col >> 6, d = col & 63;
                float2 bi = *reinterpret_cast<const float2*>(pa.bias + col);
                __half* base = pa.out + ((size_t)(bb * H_ + h) * D_) * NSEQ;
                base[(size_t)d * NSEQ + ii + g]           = __float2half_rn(acc[i][n][0] + bi.x);
                base[(size_t)(d + 1) * NSEQ + ii + g]     = __float2half_rn(acc[i][n][1] + bi.y);
                base[(size_t)d * NSEQ + ii + g + 8]       = __float2half_rn(acc[i][n][2] + bi.x);
                base[(size_t)(d + 1) * NSEQ + ii + g + 8] = __float2half_rn(acc[i][n][3] + bi.y);
            }
        }
    }
}

// outproj: A = gather(ctx half head layout), B = Wt fp16, out f32 row-major
__global__ __launch_bounds__(256, 2) void outh_kernel(OArgs2 args)
{
    const OArgs pa = args.p[blockIdx.z];
    extern __shared__ uint32_t smw[];
    const uint32_t smb = smem_u32(smw);

    const int tid  = threadIdx.x;
    const int lane = tid & 31;
    const int warp = tid >> 5;
    const int g = lane >> 2, t = lane & 3;
    const int wm = warp & 3, wn = warp >> 2;
    const int row0 = blockIdx.y * 128;
    const int col0 = blockIdx.x * 128;

    float acc[2][8][4];
    #pragma unroll
    for (int i = 0; i < 2; i++)
        #pragma unroll
        for (int n = 0; n < 8; n++)
            #pragma unroll
            for (int j = 0; j < 4; j++) acc[i][n][j] = 0.0f;

    #pragma unroll
    for (int p = 0; p < 4; p++) {
        int idx = p * 256 + tid, r = idx >> 3, c = idx & 7;
        int m = row0 + r, bb = m >> 11, ii = m & 2047;
        cp16(smb + (uint32_t)(r * GW + c * 4) * 4,
             pa.ctx + ((size_t)(bb * H_ + 0) * NSEQ + ii) * D_ + c * 8);
    }
    #pragma unroll
    for (int p = 0; p < 4; p++) {
        int idx = p * 256 + tid, r = idx >> 3, c = idx & 7;
        cp16(smb + (uint32_t)(GB_BASE + r * GW + c * 4) * 4, pa.Wt + (size_t)(col0 + r) * E_ + c * 8);
    }
    CP_COMMIT();

    int buf = 0;
    for (int kt = 0; kt < 16; kt++) {
        CP_WAIT0();
        __syncthreads();
        if (kt < 15) {
            int k0 = (kt + 1) * 64;
            int h = k0 >> 6;
            int nb = buf ^ 1;
            #pragma unroll
            for (int p = 0; p < 4; p++) {
                int idx = p * 256 + tid, r = idx >> 3, c = idx & 7;
                int m = row0 + r, bb = m >> 11, ii = m & 2047;
                cp16(smb + (uint32_t)(nb * GA_WORDS + r * GW + c * 4) * 4,
                     pa.ctx + ((size_t)(bb * H_ + h) * NSEQ + ii) * D_ + c * 8);
            }
            #pragma unroll
            for (int p = 0; p < 4; p++) {
                int idx = p * 256 + tid, r = idx >> 3, c = idx & 7;
                cp16(smb + (uint32_t)(GB_BASE + nb * GA_WORDS + r * GW + c * 4) * 4,
                     pa.Wt + (size_t)(col0 + r) * E_ + k0 + c * 8);
            }
            CP_COMMIT();
        }
        const uint32_t* A  = smw + buf * GA_WORDS;
        const uint32_t* Bm = smw + GB_BASE + buf * GA_WORDS;
        #pragma unroll
        for (int kk = 0; kk < 4; kk++) {
            uint32_t af[2][4];
            #pragma unroll
            for (int i = 0; i < 2; i++) {
                int mb = wm * 32 + i * 16;
                af[i][0] = A[(mb + g) * GW + kk * 8 + t];
                af[i][1] = A[(mb + g + 8) * GW + kk * 8 + t];
                af[i][2] = A[(mb + g) * GW + kk * 8 + t + 4];
                af[i][3] = A[(mb + g + 8) * GW + kk * 8 + t + 4];
            }
            uint32_t bf[8][2];
            #pragma unroll
            for (int n = 0; n < 8; n++) {
                bf[n][0] = Bm[(wn * 64 + n * 8 + g) * GW + kk * 8 + t];
                bf[n][1] = Bm[(wn * 64 + n * 8 + g) * GW + kk * 8 + t + 4];
            }
            #pragma unroll
            for (int i = 0; i < 2; i++)
                #pragma unroll
                for (int n = 0; n < 8; n++)
                    mma_h(acc[i][n], af[i], bf[n][0], bf[n][1]);
        }
        buf ^= 1;
    }

    #pragma unroll
    for (int i = 0; i < 2; i++) {
        int m = row0 + wm * 32 + i * 16;
        #pragma unroll
        for (int n = 0; n < 8; n++) {
            int c = col0 + wn * 64 + n * 8 + 2 * t;
            float2 bi = *reinterpret_cast<const float2*>(pa.bias + c);
            float2 lo = { acc[i][n][0] + bi.x, acc[i][n][1] + bi.y };
            float2 hi = { acc[i][n][2] + bi.x, acc[i][n][3] + bi.y };
            *reinterpret_cast<float2*>(pa.out + (size_t)(m + g) * E_ + c) = lo;
            *reinterpret_cast<float2*>(pa.out + (size_t)(m + g + 8) * E_ + c) = hi;
        }
    }
}

// ================= fp16 fused flash kernel ====================================
// Q [128][64]h, K double-buffered [128][64]h, Vt double-buffered [64][128]h,
// P [128][128]h. Word strides: Q/K 36, Vt/P 68 (conflict-free).
#define FQW 36
#define FVW 68
#define FSQ   0
#define FSK(b)  (4608 + (b)*4608)
#define FSV(b)  (13824 + (b)*4352)
#define FSP   22528
#define FLASH_WORDS 31232
#define FLASH_SMEM  (FLASH_WORDS*4)    // 124928 bytes

__global__ __launch_bounds__(256) void flashh_kernel(
    const __half* __restrict__ aq, const __half* __restrict__ bq,
    const __half* __restrict__ avt, const __half* __restrict__ bvt,
    __half* __restrict__ actx, __half* __restrict__ bctx)
{
    extern __shared__ uint32_t smw[];
    const uint32_t smb = smem_u32(smw);

    const int tid  = threadIdx.x;
    const int lane = tid & 31;
    const int warp = tid >> 5;
    const int g = lane >> 2, t = lane & 3;
    const int m0 = warp * 16;

    const int side = blockIdx.z;
    const int bh   = blockIdx.y;
    const int row0 = blockIdx.x * 128;

    const __half* Qg  = (side ? bq : aq) + (size_t)bh * NSEQ * D_;
    const __half* Kg  = (side ? aq : bq) + (size_t)bh * NSEQ * D_;
    const __half* Vtg = (side ? avt : bvt) + (size_t)bh * D_ * NSEQ;
    __half* Og = (side ? bctx : actx) + (size_t)bh * NSEQ * D_;

    // prefetch Q, K0, V0
    #pragma unroll
    for (int p = 0; p < 4; p++) {
        int idx = p * 256 + tid, r = idx >> 3, c = idx & 7;
        cp16(smb + (uint32_t)(FSQ + r * FQW + c * 4) * 4, Qg + (size_t)(row0 + r) * D_ + c * 8);
    }
    #pragma unroll
    for (int p = 0; p < 4; p++) {
        int idx = p * 256 + tid, r = idx >> 3, c = idx & 7;
        cp16(smb + (uint32_t)(FSK(0) + r * FQW + c * 4) * 4, Kg + (size_t)r * D_ + c * 8);
    }
    #pragma unroll
    for (int p = 0; p < 4; p++) {
        int idx = p * 256 + tid, r = idx >> 4, c = idx & 15;
        cp16(smb + (uint32_t)(FSV(0) + r * FVW + c * 4) * 4, Vtg + (size_t)r * NSEQ + c * 8);
    }
    CP_COMMIT();

    uint32_t Qf[4][4];
    float Oacc[8][4];
    #pragma unroll
    for (int n = 0; n < 8; n++)
        #pragma unroll
        for (int j = 0; j < 4; j++) Oacc[n][j] = 0.0f;
    float rsum0 = 0.0f, rsum1 = 0.0f;

    int buf = 0;
    for (int kt = 0; kt < 16; kt++) {
        CP_WAIT0();
        __syncthreads();
        if (kt == 0) {
            #pragma unroll
            for (int kk = 0; kk < 4; kk++) {
                Qf[kk][0] = smw[FSQ + (m0 + g) * FQW + kk * 8 + t];
                Qf[kk][1] = smw[FSQ + (m0 + g + 8) * FQW + kk * 8 + t];
                Qf[kk][2] = smw[FSQ + (m0 + g) * FQW + kk * 8 + t + 4];
                Qf[kk][3] = smw[FSQ + (m0 + g + 8) * FQW + kk * 8 + t + 4];
            }
        }
        if (kt < 15) {
            int key0 = (kt + 1) * 128;
            int nb = buf ^ 1;
            #pragma unroll
            for (int p = 0; p < 4; p++) {
                int idx = p * 256 + tid, r = idx >> 3, c = idx & 7;
                cp16(smb + (uint32_t)(FSK(nb) + r * FQW + c * 4) * 4,
                     Kg + (size_t)(key0 + r) * D_ + c * 8);
            }
            #pragma unroll
            for (int p = 0; p < 4; p++) {
                int idx = p * 256 + tid, r = idx >> 4, c = idx & 15;
                cp16(smb + (uint32_t)(FSV(nb) + r * FVW + c * 4) * 4,
                     Vtg + (size_t)r * NSEQ + key0 + c * 8);
            }
            CP_COMMIT();
        }

        const uint32_t* Ksm = smw + FSK(buf);
        const uint32_t* Vsm = smw + FSV(buf);
        uint32_t* Psm = smw + FSP;

        // MMA1: S[16,128] = Q @ K^T (4 k-steps of 16), fused exp + P + rowsum
        #pragma unroll
        for (int n = 0; n < 16; n++) {
            float c4[4] = {0.0f, 0.0f, 0.0f, 0.0f};
            #pragma unroll
            for (int kk = 0; kk < 4; kk++) {
                uint32_t b0 = Ksm[(n * 8 + g) * FQW + kk * 8 + t];
                uint32_t b1 = Ksm[(n * 8 + g) * FQW + kk * 8 + t + 4];
                mma_h(c4, Qf[kk], b0, b1);
            }
            float e0 = fexp(c4[0] * 0.125f);
            float e1 = fexp(c4[1] * 0.125f);
            float e2 = fexp(c4[2] * 0.125f);
            float e3 = fexp(c4[3] * 0.125f);
            rsum0 += e0 + e1;
            rsum1 += e2 + e3;
            Psm[(m0 + g) * FVW + n * 4 + t]     = pack_h2(e0, e1);
            Psm[(m0 + g + 8) * FVW + n * 4 + t] = pack_h2(e2, e3);
        }
        __syncwarp();

        // MMA2: O[16,64] += P @ V (8 k-steps of 16)
        #pragma unroll
        for (int kk = 0; kk < 8; kk++) {
            uint32_t a[4];
            a[0] = Psm[(m0 + g) * FVW + kk * 8 + t];
            a[1] = Psm[(m0 + g + 8) * FVW + kk * 8 + t];
            a[2] = Psm[(m0 + g) * FVW + kk * 8 + t + 4];
            a[3] = Psm[(m0 + g + 8) * FVW + kk * 8 + t + 4];
            #pragma unroll
            for (int n = 0; n < 8; n++) {
                uint32_t b0 = Vsm[(n * 8 + g) * FVW + kk * 8 + t];
                uint32_t b1 = Vsm[(n * 8 + g) * FVW + kk * 8 + t + 4];
                mma_h(Oacc[n], a, b0, b1);
            }
        }
        buf ^= 1;
    }

    rsum0 += __shfl_xor_sync(0xffffffffu, rsum0, 1);
    rsum0 += __shfl_xor_sync(0xffffffffu, rsum0, 2);
    rsum1 += __shfl_xor_sync(0xffffffffu, rsum1, 1);
    rsum1 += __shfl_xor_sync(0xffffffffu, rsum1, 2);
    float inv0 = 1.0f / rsum0;
    float inv1 = 1.0f / rsum1;

    __half* r0p = Og + (size_t)(row0 + m0 + g) * D_;
    __half* r1p = Og + (size_t)(row0 + m0 + g + 8) * D_;
    #pragma unroll
    for (int n = 0; n < 8; n++) {
        *reinterpret_cast<uint32_t*>(r0p + n * 8 + 2 * t) =
            pack_h2(Oacc[n][0] * inv0, Oacc[n][1] * inv0);
        *reinterpret_cast<uint32_t*>(r1p + n * 8 + 2 * t) =
            pack_h2(Oacc[n][2] * inv1, Oacc[n][3] * inv1);
    }
}

// ---------------------------------------------------------------------------
extern "C" void kernel_launch(void* const* d_in, const int* in_sizes, int n_in,
                              void* d_out, int out_size)
{
    (void)in_sizes; (void)n_in; (void)out_size;
    const float* a     = (const float*)d_in[0];
    const float* b     = (const float*)d_in[1];
    const float* Wa_qk = (const float*)d_in[2];
    const float* ba_qk = (const float*)d_in[3];
    const float* Wa_v  = (const float*)d_in[4];
    const float* ba_v  = (const float*)d_in[5];
    const float* Wb_qk = (const float*)d_in[6];
    const float* bb_qk = (const float*)d_in[7];
    const float* Wb_v  = (const float*)d_in[8];
    const float* bb_v  = (const float*)d_in[9];
    const float* Wa_o  = (const float*)d_in[10];
    const float* ba_o  = (const float*)d_in[11];
    const float* Wb_o  = (const float*)d_in[12];
    const float* bb_o  = (const float*)d_in[13];
    float* out = (float*)d_out;

    float* scratch = nullptr;
    cudaGetSymbolAddress((void**)&scratch, g_scratch);
    __half* aqh  = (__half*)(scratch + OFF_AQ);
    __half* bqh  = (__half*)(scratch + OFF_BQ);
    __half* avt  = (__half*)(scratch + OFF_AVT);
    __half* bvt  = (__half*)(scratch + OFF_BVT);
    __half* actx = (__half*)(scratch + OFF_ACTX);
    __half* bctx = (__half*)(scratch + OFF_BCTX);
    __half* aTh  = (__half*)(scratch + OFF_ATH);
    __half* bTh  = (__half*)(scratch + OFF_BTH);
    __half* wTh  = (__half*)(scratch + OFF_WT);

    cudaFuncSetAttribute(projh_kernel,  cudaFuncAttributeMaxDynamicSharedMemorySize, GEMM_SMEM);
    cudaFuncSetAttribute(outh_kernel,   cudaFuncAttributeMaxDynamicSharedMemorySize, GEMM_SMEM);
    cudaFuncSetAttribute(flashh_kernel, cudaFuncAttributeMaxDynamicSharedMemorySize, FLASH_SMEM);

    // inputs -> fp16
    cvth_kernel<<<1024, 256>>>((const float4*)a, (uint2*)aTh, 1048576);
    cvth_kernel<<<1024, 256>>>((const float4*)b, (uint2*)bTh, 1048576);
    // weights -> transposed fp16
    dim3 tg(32, 32);
    wtrans_kernel<<<tg, 256>>>(Wa_qk, wTh + 0 * 1048576);
    wtrans_kernel<<<tg, 256>>>(Wa_v,  wTh + 1 * 1048576);
    wtrans_kernel<<<tg, 256>>>(Wb_qk, wTh + 2 * 1048576);
    wtrans_kernel<<<tg, 256>>>(Wb_v,  wTh + 3 * 1048576);
    wtrans_kernel<<<tg, 256>>>(Wa_o,  wTh + 4 * 1048576);
    wtrans_kernel<<<tg, 256>>>(Wb_o,  wTh + 5 * 1048576);

    PArgs4 pargs;
    pargs.p[0] = { aTh, wTh + 0 * 1048576, ba_qk, aqh, 0 };
    pargs.p[1] = { aTh, wTh + 1 * 1048576, ba_v,  avt, 1 };
    pargs.p[2] = { bTh, wTh + 2 * 1048576, bb_qk, bqh, 0 };
    pargs.p[3] = { bTh, wTh + 3 * 1048576, bb_v,  bvt, 1 };
    projh_kernel<<<dim3(E_ / 128, (B_ * NSEQ) / 128, 4), 256, GEMM_SMEM>>>(pargs);

    flashh_kernel<<<dim3(16, BH_, 2), 256, FLASH_SMEM>>>(aqh, bqh, avt, bvt, actx, bctx);

    OArgs2 oargs;
    oargs.p[0] = { actx, wTh + 4 * 1048576, ba_o, out };
    oargs.p[1] = { bctx, wTh + 5 * 1048576, bb_o, out + (size_t)B_ * NSEQ * E_ };
    outh_kernel<<<dim3(E_ / 128, (B_ * NSEQ) / 128, 2), 256, GEMM_SMEM>>>(oargs);
}

// round 7
// speedup vs baseline: 8.9237x; 1.8744x over previous
#include <cuda_runtime.h>
#include <cuda_fp16.h>
#include <math.h>
#include <stdint.h>

#define B_    2
#define H_    16
#define E_    1024
#define D_    64
#define BH_   32
#define NSEQ  2048

// ---------------- scratch (float units; halves live inside) ------------------
static const size_t OFF_AQ   = 0;                   // half [32][2048][64]
static const size_t OFF_BQ   = OFF_AQ   + 2097152;
static const size_t OFF_AVT  = OFF_BQ   + 2097152;  // half [32][64][2048]
static const size_t OFF_BVT  = OFF_AVT  + 2097152;
static const size_t OFF_ACTX = OFF_BVT  + 2097152;  // half [32][2048][64]
static const size_t OFF_BCTX = OFF_ACTX + 2097152;
static const size_t OFF_ATH  = OFF_BCTX + 2097152;  // half [4096][1024]
static const size_t OFF_BTH  = OFF_ATH  + 2097152;
static const size_t OFF_WT   = OFF_BTH  + 2097152;  // 6x half [1024n][1024k]
static const size_t SCRATCH_ELEMS = OFF_WT + 6 * 524288;
__device__ float g_scratch[SCRATCH_ELEMS];

// ---------------- helpers ----------------------------------------------------
__device__ __forceinline__ float ex2f(float x) {
    float y;
    asm("ex2.approx.f32 %0, %1;" : "=f"(y) : "f"(x));
    return y;
}
#define CEXP 0.18033688011112042f   // log2(e)/8 : exp(s/8) = 2^(s*CEXP)

__device__ __forceinline__ uint32_t pack_h2(float lo, float hi) {
    __half2 h = __floats2half2_rn(lo, hi);
    return *reinterpret_cast<uint32_t*>(&h);
}

__device__ __forceinline__ uint32_t smem_u32(const void* p) {
    uint32_t a;
    asm("{ .reg .u64 t; cvta.to.shared.u64 t, %1; cvt.u32.u64 %0, t; }" : "=r"(a) : "l"(p));
    return a;
}

__device__ __forceinline__ void mma_h(float c[4], const uint32_t a[4],
                                      uint32_t b0, uint32_t b1) {
    asm volatile(
        "mma.sync.aligned.m16n8k16.row.col.f32.f16.f16.f32 "
        "{%0,%1,%2,%3}, {%4,%5,%6,%7}, {%8,%9}, {%0,%1,%2,%3};"
        : "+f"(c[0]), "+f"(c[1]), "+f"(c[2]), "+f"(c[3])
        : "r"(a[0]), "r"(a[1]), "r"(a[2]), "r"(a[3]), "r"(b0), "r"(b1));
}

#define LDMX4(r0, r1, r2, r3, addr) \
    asm volatile("ldmatrix.sync.aligned.m8n8.x4.shared.b16 {%0,%1,%2,%3}, [%4];" \
        : "=r"(r0), "=r"(r1), "=r"(r2), "=r"(r3) : "r"(addr))

__device__ __forceinline__ void cp16(uint32_t dst, const void* src) {
    asm volatile("cp.async.cg.shared.global [%0], [%1], 16;" :: "r"(dst), "l"(src) : "memory");
}
#define CP_COMMIT() asm volatile("cp.async.commit_group;" ::: "memory")
#define CP_WAIT0()  asm volatile("cp.async.wait_group 0;" ::: "memory")

// ---------------- merged prologue: cvt a,b + 6 weight transposes -------------
struct PrepArgs {
    const float *a, *b, *W0, *W1, *W2, *W3, *W4, *W5;
    __half *aTh, *bTh, *wTh;
};

__global__ __launch_bounds__(256) void prep_kernel(PrepArgs pa)
{
    __shared__ float tile[32][33];
    const int z = blockIdx.z;
    const int tid = threadIdx.x;
    if (z < 2) {
        const float4* src = (const float4*)(z ? pa.b : pa.a);
        uint2* dst = (uint2*)(z ? pa.bTh : pa.aTh);
        int i = (blockIdx.y * 32 + blockIdx.x) * 256 + tid;
        #pragma unroll
        for (int r = 0; r < 4; r++) {
            float4 v = src[i];
            uint2 o = { pack_h2(v.x, v.y), pack_h2(v.z, v.w) };
            dst[i] = o;
            i += 262144;
        }
    } else {
        const float* W = (z == 2) ? pa.W0 : (z == 3) ? pa.W1 : (z == 4) ? pa.W2 :
                         (z == 5) ? pa.W3 : (z == 6) ? pa.W4 : pa.W5;
        __half* Wt = pa.wTh + (size_t)(z - 2) * 1048576;
        const int n0 = blockIdx.x * 32, k0 = blockIdx.y * 32;
        const int tx = tid & 31, ty = tid >> 5;
        #pragma unroll
        for (int j = 0; j < 4; j++)
            tile[ty + 8 * j][tx] = W[(size_t)(k0 + ty + 8 * j) * E_ + n0 + tx];
        __syncthreads();
        #pragma unroll
        for (int j = 0; j < 4; j++)
            Wt[(size_t)(n0 + ty + 8 * j) * E_ + k0 + tx] = __float2half_rn(tile[tx][ty + 8 * j]);
    }
}

// ================= fp16 GEMMs (ldmatrix + cp.async) ==========================
#define GW 36
#define GA_WORDS (128*GW)
#define GB_BASE  (2*GA_WORDS)
#define GEMM_SMEM (4*GA_WORDS*4)     // 73728 bytes

struct PArgs { const __half* X; const __half* Wt; const float* bias; __half* out; int vmode; };
struct PArgs4 { PArgs p[4]; };
struct OArgs { const __half* ctx; const __half* Wt; const float* bias; float* out; };
struct OArgs2 { OArgs p[2]; };

__global__ __launch_bounds__(256, 2) void projh_kernel(PArgs4 args)
{
    const PArgs pa = args.p[blockIdx.z];
    extern __shared__ uint32_t smw[];
    const uint32_t smb = smem_u32(smw);

    const int tid  = threadIdx.x;
    const int lane = tid & 31;
    const int warp = tid >> 5;
    const int g = lane >> 2, t = lane & 3;
    const int l8 = lane & 7, quad = lane >> 3;
    const int wm = warp & 3, wn = warp >> 2;
    const int row0 = blockIdx.y * 128;
    const int col0 = blockIdx.x * 128;

    const uint32_t aoff = (uint32_t)((((quad & 1) * 8 + l8) * GW + (quad >> 1) * 4) * 4);
    const uint32_t boff = (uint32_t)((((quad >> 1) * 8 + l8) * GW + (quad & 1) * 4) * 4);

    float acc[2][8][4];
    #pragma unroll
    for (int i = 0; i < 2; i++)
        #pragma unroll
        for (int n = 0; n < 8; n++)
            #pragma unroll
            for (int j = 0; j < 4; j++) acc[i][n][j] = 0.0f;

    #pragma unroll
    for (int p = 0; p < 4; p++) {
        int idx = p * 256 + tid, r = idx >> 3, c = idx & 7;
        cp16(smb + (uint32_t)(r * GW + c * 4) * 4, pa.X + (size_t)(row0 + r) * E_ + c * 8);
    }
    #pragma unroll
    for (int p = 0; p < 4; p++) {
        int idx = p * 256 + tid, r = idx >> 3, c = idx & 7;
        cp16(smb + (uint32_t)(GB_BASE + r * GW + c * 4) * 4, pa.Wt + (size_t)(col0 + r) * E_ + c * 8);
    }
    CP_COMMIT();

    int buf = 0;
    for (int kt = 0; kt < 16; kt++) {
        CP_WAIT0();
        __syncthreads();
        if (kt < 15) {
            int k0 = (kt + 1) * 64;
            int nb = buf ^ 1;
            #pragma unroll
            for (int p = 0; p < 4; p++) {
                int idx = p * 256 + tid, r = idx >> 3, c = idx & 7;
                cp16(smb + (uint32_t)(nb * GA_WORDS + r * GW + c * 4) * 4,
                     pa.X + (size_t)(row0 + r) * E_ + k0 + c * 8);
            }
            #pragma unroll
            for (int p = 0; p < 4; p++) {
                int idx = p * 256 + tid, r = idx >> 3, c = idx & 7;
                cp16(smb + (uint32_t)(GB_BASE + nb * GA_WORDS + r * GW + c * 4) * 4,
                     pa.Wt + (size_t)(col0 + r) * E_ + k0 + c * 8);
            }
            CP_COMMIT();
        }
        const uint32_t aBuf = smb + (uint32_t)(buf * GA_WORDS) * 4;
        const uint32_t bBuf = smb + (uint32_t)(GB_BASE + buf * GA_WORDS) * 4;
        #pragma unroll
        for (int kk = 0; kk < 4; kk++) {
            uint32_t af[2][4];
            LDMX4(af[0][0], af[0][1], af[0][2], af[0][3],
                  aBuf + aoff + (uint32_t)((wm * 32) * GW + kk * 8) * 4);
            LDMX4(af[1][0], af[1][1], af[1][2], af[1][3],
                  aBuf + aoff + (uint32_t)((wm * 32 + 16) * GW + kk * 8) * 4);
            #pragma unroll
            for (int j = 0; j < 4; j++) {
                uint32_t r0, r1, r2, r3;
                LDMX4(r0, r1, r2, r3,
                      bBuf + boff + (uint32_t)((wn * 64 + j * 16) * GW + kk * 8) * 4);
                mma_h(acc[0][2 * j],     af[0], r0, r1);
                mma_h(acc[0][2 * j + 1], af[0], r2, r3);
                mma_h(acc[1][2 * j],     af[1], r0, r1);
                mma_h(acc[1][2 * j + 1], af[1], r2, r3);
            }
        }
        buf ^= 1;
    }

    if (!pa.vmode) {
        #pragma unroll
        for (int i = 0; i < 2; i++) {
            int m = row0 + wm * 32 + i * 16;
            int bb = m >> 11, ii = m & 2047;
            #pragma unroll
            for (int n = 0; n < 8; n++) {
                int col = col0 + wn * 64 + n * 8 + 2 * t;
                int h = col >> 6, d = col & 63;
                float2 bi = *reinterpret_cast<const float2*>(pa.bias + col);
                __half* base = pa.out + ((size_t)(bb * H_ + h) * NSEQ) * D_ + d;
                *reinterpret_cast<uint32_t*>(base + (size_t)(ii + g) * D_) =
                    pack_h2(acc[i][n][0] + bi.x, acc[i][n][1] + bi.y);
                *reinterpret_cast<uint32_t*>(base + (size_t)(ii + g + 8) * D_) =
                    pack_h2(acc[i][n][2] + bi.x, acc[i][n][3] + bi.y);
            }
        }
    } else {
        #pragma unroll
        for (int i = 0; i < 2; i++) {
            int m = row0 + wm * 32 + i * 16;
            int bb = m >> 11, ii = m & 2047;
            #pragma unroll
            for (int n = 0; n < 8; n++) {
                int col = col0 + wn * 64 + n * 8 + 2 * t;
                int h = col >> 6, d = col & 63;
                float2 bi = *reinterpret_cast<const float2*>(pa.bias + col);
                __half* base = pa.out + ((size_t)(bb * H_ + h) * D_) * NSEQ;
                base[(size_t)d * NSEQ + ii + g]           = __float2half_rn(acc[i][n][0] + bi.x);
                base[(size_t)(d + 1) * NSEQ + ii + g]     = __float2half_rn(acc[i][n][1] + bi.y);
                base[(size_t)d * NSEQ + ii + g + 8]       = __float2half_rn(acc[i][n][2] + bi.x);
                base[(size_t)(d + 1) * NSEQ + ii + g + 8] = __float2half_rn(acc[i][n][3] + bi.y);
            }
        }
    }
}

__global__ __launch_bounds__(256, 2) void outh_kernel(OArgs2 args)
{
    const OArgs pa = args.p[blockIdx.z];
    extern __shared__ uint32_t smw[];
    const uint32_t smb = smem_u32(smw);

    const int tid  = threadIdx.x;
    const int lane = tid & 31;
    const int warp = tid >> 5;
    const int g = lane >> 2, t = lane & 3;
    const int l8 = lane & 7, quad = lane >> 3;
    const int wm = warp & 3, wn = warp >> 2;
    const int row0 = blockIdx.y * 128;
    const int col0 = blockIdx.x * 128;

    const uint32_t aoff = (uint32_t)((((quad & 1) * 8 + l8) * GW + (quad >> 1) * 4) * 4);
    const uint32_t boff = (uint32_t)((((quad >> 1) * 8 + l8) * GW + (quad & 1) * 4) * 4);

    float acc[2][8][4];
    #pragma unroll
    for (int i = 0; i < 2; i++)
        #pragma unroll
        for (int n = 0; n < 8; n++)
            #pragma unroll
            for (int j = 0; j < 4; j++) acc[i][n][j] = 0.0f;

    #pragma unroll
    for (int p = 0; p < 4; p++) {
        int idx = p * 256 + tid, r = idx >> 3, c = idx & 7;
        int m = row0 + r, bb = m >> 11, ii = m & 2047;
        cp16(smb + (uint32_t)(r * GW + c * 4) * 4,
             pa.ctx + ((size_t)(bb * H_) * NSEQ + ii) * D_ + c * 8);
    }
    #pragma unroll
    for (int p = 0; p < 4; p++) {
        int idx = p * 256 + tid, r = idx >> 3, c = idx & 7;
        cp16(smb + (uint32_t)(GB_BASE + r * GW + c * 4) * 4, pa.Wt + (size_t)(col0 + r) * E_ + c * 8);
    }
    CP_COMMIT();

    int buf = 0;
    for (int kt = 0; kt < 16; kt++) {
        CP_WAIT0();
        __syncthreads();
        if (kt < 15) {
            int k0 = (kt + 1) * 64;
            int h = k0 >> 6;
            int nb = buf ^ 1;
            #pragma unroll
            for (int p = 0; p < 4; p++) {
                int idx = p * 256 + tid, r = idx >> 3, c = idx & 7;
                int m = row0 + r, bb = m >> 11, ii = m & 2047;
                cp16(smb + (uint32_t)(nb * GA_WORDS + r * GW + c * 4) * 4,
                     pa.ctx + ((size_t)(bb * H_ + h) * NSEQ + ii) * D_ + c * 8);
            }
            #pragma unroll
            for (int p = 0; p < 4; p++) {
                int idx = p * 256 + tid, r = idx >> 3, c = idx & 7;
                cp16(smb + (uint32_t)(GB_BASE + nb * GA_WORDS + r * GW + c * 4) * 4,
                     pa.Wt + (size_t)(col0 + r) * E_ + k0 + c * 8);
            }
            CP_COMMIT();
        }
        const uint32_t aBuf = smb + (uint32_t)(buf * GA_WORDS) * 4;
        const uint32_t bBuf = smb + (uint32_t)(GB_BASE + buf * GA_WORDS) * 4;
        #pragma unroll
        for (int kk = 0; kk < 4; kk++) {
            uint32_t af[2][4];
            LDMX4(af[0][0], af[0][1], af[0][2], af[0][3],
                  aBuf + aoff + (uint32_t)((wm * 32) * GW + kk * 8) * 4);
            LDMX4(af[1][0], af[1][1], af[1][2], af[1][3],
                  aBuf + aoff + (uint32_t)((wm * 32 + 16) * GW + kk * 8) * 4);
            #pragma unroll
            for (int j = 0; j < 4; j++) {
                uint32_t r0, r1, r2, r3;
                LDMX4(r0, r1, r2, r3,
                      bBuf + boff + (uint32_t)((wn * 64 + j * 16) * GW + kk * 8) * 4);
                mma_h(acc[0][2 * j],     af[0], r0, r1);
                mma_h(acc[0][2 * j + 1], af[0], r2, r3);
                mma_h(acc[1][2 * j],     af[1], r0, r1);
                mma_h(acc[1][2 * j + 1], af[1], r2, r3);
            }
        }
        buf ^= 1;
    }

    #pragma unroll
    for (int i = 0; i < 2; i++) {
        int m = row0 + wm * 32 + i * 16;
        #pragma unroll
        for (int n = 0; n < 8; n++) {
            int c = col0 + wn * 64 + n * 8 + 2 * t;
            float2 bi = *reinterpret_cast<const float2*>(pa.bias + c);
            float2 lo = { acc[i][n][0] + bi.x, acc[i][n][1] + bi.y };
            float2 hi = { acc[i][n][2] + bi.x, acc[i][n][3] + bi.y };
            *reinterpret_cast<float2*>(pa.out + (size_t)(m + g) * E_ + c) = lo;
            *reinterpret_cast<float2*>(pa.out + (size_t)(m + g + 8) * E_ + c) = hi;
        }
    }
}

// ================= fused flash kernel: register-passed P =====================
// Q [128][64]h stride-36w, K dbuf [128][64]h stride-36w, Vt dbuf [64][128]h
// stride-68w. P never touches smem: MMA1 C-fragment -> exp -> MMA2 A-fragment.
#define FQW 36
#define FVW 68
#define FSQ   0
#define FSKa  4608
#define FSVa  13824
#define FLASH_WORDS 22528
#define FLASH_SMEM  (FLASH_WORDS*4)   // 90112 bytes -> 2 CTA/SM

__global__ __launch_bounds__(256, 2) void flashh_kernel(
    const __half* __restrict__ aq, const __half* __restrict__ bq,
    const __half* __restrict__ avt, const __half* __restrict__ bvt,
    __half* __restrict__ actx, __half* __restrict__ bctx)
{
    extern __shared__ uint32_t smw[];
    const uint32_t smb = smem_u32(smw);

    const int tid  = threadIdx.x;
    const int lane = tid & 31;
    const int warp = tid >> 5;
    const int g = lane >> 2, t = lane & 3;
    const int l8 = lane & 7, quad = lane >> 3;
    const int m0 = warp * 16;

    const int side = blockIdx.z;
    const int bh   = blockIdx.y;
    const int row0 = blockIdx.x * 128;

    const __half* Qg  = (side ? bq : aq) + (size_t)bh * NSEQ * D_;
    const __half* Kg  = (side ? aq : bq) + (size_t)bh * NSEQ * D_;
    const __half* Vtg = (side ? avt : bvt) + (size_t)bh * D_ * NSEQ;
    __half* Og = (side ? bctx : actx) + (size_t)bh * NSEQ * D_;

    // ldmatrix per-thread offsets (bytes)
    const uint32_t koff = (uint32_t)((((quad >> 1) * 8 + l8) * FQW + (quad & 1) * 4) * 4);
    const uint32_t voff = (uint32_t)((((quad >> 1) * 8 + l8) * FVW + (quad & 1) * 4) * 4);

    // prefetch Q, K0, V0
    #pragma unroll
    for (int p = 0; p < 4; p++) {
        int idx = p * 256 + tid, r = idx >> 3, c = idx & 7;
        cp16(smb + (uint32_t)(FSQ + r * FQW + c * 4) * 4, Qg + (size_t)(row0 + r) * D_ + c * 8);
    }
    #pragma unroll
    for (int p = 0; p < 4; p++) {
        int idx = p * 256 + tid, r = idx >> 3, c = idx & 7;
        cp16(smb + (uint32_t)(FSKa + r * FQW + c * 4) * 4, Kg + (size_t)r * D_ + c * 8);
    }
    #pragma unroll
    for (int p = 0; p < 4; p++) {
        int idx = p * 256 + tid, r = idx >> 4, c = idx & 15;
        cp16(smb + (uint32_t)(FSVa + r * FVW + c * 4) * 4, Vtg + (size_t)r * NSEQ + c * 8);
    }
    CP_COMMIT();

    uint32_t Qf[4][4];
    float Oacc[8][4];
    #pragma unroll
    for (int n = 0; n < 8; n++)
        #pragma unroll
        for (int j = 0; j < 4; j++) Oacc[n][j] = 0.0f;
    float rsum0 = 0.0f, rsum1 = 0.0f;

    int buf = 0;
    for (int kt = 0; kt < 16; kt++) {
        CP_WAIT0();
        __syncthreads();
        if (kt == 0) {
            #pragma unroll
            for (int kk = 0; kk < 4; kk++) {
                Qf[kk][0] = smw[FSQ + (m0 + g) * FQW + kk * 8 + t];
                Qf[kk][1] = smw[FSQ + (m0 + g + 8) * FQW + kk * 8 + t];
                Qf[kk][2] = smw[FSQ + (m0 + g) * FQW + kk * 8 + t + 4];
                Qf[kk][3] = smw[FSQ + (m0 + g + 8) * FQW + kk * 8 + t + 4];
            }
        }
        if (kt < 15) {
            int key0 = (kt + 1) * 128;
            int nb = buf ^ 1;
            #pragma unroll
            for (int p = 0; p < 4; p++) {
                int idx = p * 256 + tid, r = idx >> 3, c = idx & 7;
                cp16(smb + (uint32_t)(FSKa + nb * 4608 + r * FQW + c * 4) * 4,
                     Kg + (size_t)(key0 + r) * D_ + c * 8);
            }
            #pragma unroll
            for (int p = 0; p < 4; p++) {
                int idx = p * 256 + tid, r = idx >> 4, c = idx & 15;
                cp16(smb + (uint32_t)(FSVa + nb * 4352 + r * FVW + c * 4) * 4,
                     Vtg + (size_t)r * NSEQ + key0 + c * 8);
            }
            CP_COMMIT();
        }

        const uint32_t kbase = smb + (uint32_t)(FSKa + buf * 4608) * 4 + koff;
        const uint32_t vbase = smb + (uint32_t)(FSVa + buf * 4352) * 4 + voff;

        #pragma unroll
        for (int kk = 0; kk < 8; kk++) {
            // MMA1: two 8-col score tiles = keys 16kk..16kk+15
            float slo[4] = {0.f, 0.f, 0.f, 0.f};
            float shi[4] = {0.f, 0.f, 0.f, 0.f};
            #pragma unroll
            for (int c = 0; c < 4; c++) {
                uint32_t r0, r1, r2, r3;
                LDMX4(r0, r1, r2, r3, kbase + (uint32_t)((16 * kk) * FQW + c * 8) * 4);
                mma_h(slo, Qf[c], r0, r1);
                mma_h(shi, Qf[c], r2, r3);
            }
            // exp (MUFU) + rowsum + pack into MMA2 A-fragment
            float e0 = ex2f(slo[0] * CEXP), e1 = ex2f(slo[1] * CEXP);
            float e2 = ex2f(slo[2] * CEXP), e3 = ex2f(slo[3] * CEXP);
            float f0 = ex2f(shi[0] * CEXP), f1 = ex2f(shi[1] * CEXP);
            float f2 = ex2f(shi[2] * CEXP), f3 = ex2f(shi[3] * CEXP);
            rsum0 += (e0 + e1) + (f0 + f1);
            rsum1 += (e2 + e3) + (f2 + f3);
            uint32_t a[4] = { pack_h2(e0, e1), pack_h2(e2, e3),
                              pack_h2(f0, f1), pack_h2(f2, f3) };
            // MMA2: O[16,64] += P_slab @ V_slab
            #pragma unroll
            for (int j = 0; j < 4; j++) {
                uint32_t r0, r1, r2, r3;
                LDMX4(r0, r1, r2, r3, vbase + (uint32_t)((16 * j) * FVW + kk * 8) * 4);
                mma_h(Oacc[2 * j],     a, r0, r1);
                mma_h(Oacc[2 * j + 1], a, r2, r3);
            }
        }
        buf ^= 1;
    }

    rsum0 += __shfl_xor_sync(0xffffffffu, rsum0, 1);
    rsum0 += __shfl_xor_sync(0xffffffffu, rsum0, 2);
    rsum1 += __shfl_xor_sync(0xffffffffu, rsum1, 1);
    rsum1 += __shfl_xor_sync(0xffffffffu, rsum1, 2);
    float inv0 = 1.0f / rsum0;
    float inv1 = 1.0f / rsum1;

    __half* r0p = Og + (size_t)(row0 + m0 + g) * D_;
    __half* r1p = Og + (size_t)(row0 + m0 + g + 8) * D_;
    #pragma unroll
    for (int n = 0; n < 8; n++) {
        *reinterpret_cast<uint32_t*>(r0p + n * 8 + 2 * t) =
            pack_h2(Oacc[n][0] * inv0, Oacc[n][1] * inv0);
        *reinterpret_cast<uint32_t*>(r1p + n * 8 + 2 * t) =
            pack_h2(Oacc[n][2] * inv1, Oacc[n][3] * inv1);
    }
}

// ---------------------------------------------------------------------------
extern "C" void kernel_launch(void* const* d_in, const int* in_sizes, int n_in,
                              void* d_out, int out_size)
{
    (void)in_sizes; (void)n_in; (void)out_size;
    const float* a     = (const float*)d_in[0];
    const float* b     = (const float*)d_in[1];
    const float* Wa_qk = (const float*)d_in[2];
    const float* ba_qk = (const float*)d_in[3];
    const float* Wa_v  = (const float*)d_in[4];
    const float* ba_v  = (const float*)d_in[5];
    const float* Wb_qk = (const float*)d_in[6];
    const float* bb_qk = (const float*)d_in[7];
    const float* Wb_v  = (const float*)d_in[8];
    const float* bb_v  = (const float*)d_in[9];
    const float* Wa_o  = (const float*)d_in[10];
    const float* ba_o  = (const float*)d_in[11];
    const float* Wb_o  = (const float*)d_in[12];
    const float* bb_o  = (const float*)d_in[13];
    float* out = (float*)d_out;

    float* scratch = nullptr;
    cudaGetSymbolAddress((void**)&scratch, g_scratch);
    __half* aqh  = (__half*)(scratch + OFF_AQ);
    __half* bqh  = (__half*)(scratch + OFF_BQ);
    __half* avt  = (__half*)(scratch + OFF_AVT);
    __half* bvt  = (__half*)(scratch + OFF_BVT);
    __half* actx = (__half*)(scratch + OFF_ACTX);
    __half* bctx = (__half*)(scratch + OFF_BCTX);
    __half* aTh  = (__half*)(scratch + OFF_ATH);
    __half* bTh  = (__half*)(scratch + OFF_BTH);
    __half* wTh  = (__half*)(scratch + OFF_WT);

    cudaFuncSetAttribute(projh_kernel,  cudaFuncAttributeMaxDynamicSharedMemorySize, GEMM_SMEM);
    cudaFuncSetAttribute(outh_kernel,   cudaFuncAttributeMaxDynamicSharedMemorySize, GEMM_SMEM);
    cudaFuncSetAttribute(flashh_kernel, cudaFuncAttributeMaxDynamicSharedMemorySize, FLASH_SMEM);

    PrepArgs prep = { a, b, Wa_qk, Wa_v, Wb_qk, Wb_v, Wa_o, Wb_o, aTh, bTh, wTh };
    prep_kernel<<<dim3(32, 32, 8), 256>>>(prep);

    PArgs4 pargs;
    pargs.p[0] = { aTh, wTh + 0 * 1048576, ba_qk, aqh, 0 };
    pargs.p[1] = { aTh, wTh + 1 * 1048576, ba_v,  avt, 1 };
    pargs.p[2] = { bTh, wTh + 2 * 1048576, bb_qk, bqh, 0 };
    pargs.p[3] = { bTh, wTh + 3 * 1048576, bb_v,  bvt, 1 };
    projh_kernel<<<dim3(E_ / 128, (B_ * NSEQ) / 128, 4), 256, GEMM_SMEM>>>(pargs);

    flashh_kernel<<<dim3(16, BH_, 2), 256, FLASH_SMEM>>>(aqh, bqh, avt, bvt, actx, bctx);

    OArgs2 oargs;
    oargs.p[0] = { actx, wTh + 4 * 1048576, ba_o, out };
    oargs.p[1] = { bctx, wTh + 5 * 1048576, bb_o, out + (size_t)B_ * NSEQ * E_ };
    outh_kernel<<<dim3(E_ / 128, (B_ * NSEQ) / 128, 2), 256, GEMM_SMEM>>>(oargs);
}